// round 2
// baseline (speedup 1.0000x reference)
#include <cuda_runtime.h>
#include <cuda_bf16.h>
#include <float.h>

// Problem constants (shapes fixed by the dataset)
#define BATCH 4
#define NPT   16384
#define SPT   2048
#define KNN   16
#define DFEAT 125
#define C0    128
#define C1    128
#define C2    256
#define MROWS (BATCH * SPT * KNN)   // 131072 samples through the MLP

// ---------------- scratch (static device globals; no allocation allowed) ----
__device__ float g_x1[(size_t)MROWS * C0];     // 67 MB  gathered/concat input
__device__ float g_y1[(size_t)MROWS * C1];     // 67 MB  conv1 out -> bn1relu in place
__device__ float g_y2[(size_t)MROWS * C2];     // 134 MB conv2 out
__device__ float g_part[2 * 256 * 256];        // partial sums: [sum | sumsq], 256 blocks x C
__device__ float g_scale[256];
__device__ float g_bias[256];
__device__ int   g_fps[BATCH * SPT];
__device__ int   g_knn[BATCH * SPT * KNN];

// ============================================================================
// 1) Farthest point sampling. One block per batch, 1024 threads, 16 pts/thread
//    in registers. Must match jnp argmax semantics exactly:
//    - distance formula without FMA contraction: (dx*dx + dy*dy) + dz*dz
//    - tie-break: max value, then smallest index
//    - emits the farthest index of the PREVIOUS step (selected[0] = 0)
// ============================================================================
__global__ __launch_bounds__(1024, 1)
void fps_kernel(const float* __restrict__ xyz, int* __restrict__ fps_idx,
                float* __restrict__ new_xyz) {
    int b = blockIdx.x;
    int t = threadIdx.x;
    const float* p = xyz + (size_t)b * NPT * 3;

    float px[16], py[16], pz[16], dist[16];
#pragma unroll
    for (int j = 0; j < 16; j++) {
        int i = t + j * 1024;
        px[j] = p[i * 3 + 0];
        py[j] = p[i * 3 + 1];
        pz[j] = p[i * 3 + 2];
        dist[j] = 1e10f;
    }

    __shared__ float rv[32];
    __shared__ int   ri[32];
    __shared__ int   sfar;

    int warp = t >> 5, lane = t & 31;
    int far = 0;

    for (int s = 0; s < SPT; s++) {
        float cx = p[far * 3 + 0];
        float cy = p[far * 3 + 1];
        float cz = p[far * 3 + 2];
        if (t == 0) {
            fps_idx[b * SPT + s] = far;
            new_xyz[((size_t)b * SPT + s) * 3 + 0] = cx;
            new_xyz[((size_t)b * SPT + s) * 3 + 1] = cy;
            new_xyz[((size_t)b * SPT + s) * 3 + 2] = cz;
        }
        float best = -1.0f;
        int   bi   = 0;
#pragma unroll
        for (int j = 0; j < 16; j++) {
            float dx = px[j] - cx, dy = py[j] - cy, dz = pz[j] - cz;
            float d = __fadd_rn(__fadd_rn(__fmul_rn(dx, dx), __fmul_rn(dy, dy)),
                                __fmul_rn(dz, dz));
            float nd = fminf(dist[j], d);
            dist[j] = nd;
            if (nd > best) { best = nd; bi = t + j * 1024; }
        }
        // warp reduce: max value, tie -> smaller index
#pragma unroll
        for (int off = 16; off; off >>= 1) {
            float ov = __shfl_down_sync(0xffffffffu, best, off);
            int   oi = __shfl_down_sync(0xffffffffu, bi, off);
            if (ov > best || (ov == best && oi < bi)) { best = ov; bi = oi; }
        }
        if (lane == 0) { rv[warp] = best; ri[warp] = bi; }
        __syncthreads();
        if (warp == 0) {
            best = rv[lane]; bi = ri[lane];
#pragma unroll
            for (int off = 16; off; off >>= 1) {
                float ov = __shfl_down_sync(0xffffffffu, best, off);
                int   oi = __shfl_down_sync(0xffffffffu, bi, off);
                if (ov > best || (ov == best && oi < bi)) { best = ov; bi = oi; }
            }
            if (lane == 0) sfar = bi;
        }
        __syncthreads();
        far = sfar;
    }
}

// ============================================================================
// 2) kNN (k=16). One warp per query; each lane keeps a register top-16 over
//    512 strided points, then 512 -> 16 selection through shared memory.
//    Only the SET of neighbors matters downstream (max-pool is order-free).
// ============================================================================
__global__ __launch_bounds__(256, 1)
void knn_kernel(const float* __restrict__ xyz, const float* __restrict__ new_xyz,
                int* __restrict__ knn) {
    __shared__ float sd[8][512];
    __shared__ int   si[8][512];
    int w = threadIdx.x >> 5, lane = threadIdx.x & 31;
    int g = blockIdx.x * 8 + w;     // query id 0..8191
    int b = g >> 11;
    const float* p = xyz + (size_t)b * NPT * 3;
    float qx = new_xyz[(size_t)g * 3 + 0];
    float qy = new_xyz[(size_t)g * 3 + 1];
    float qz = new_xyz[(size_t)g * 3 + 2];

    float d16[16]; int i16[16];
#pragma unroll
    for (int t = 0; t < 16; t++) { d16[t] = FLT_MAX; i16[t] = 0; }
    float worst = FLT_MAX; int wpos = 0;

    for (int i = 0; i < NPT / 32; i++) {
        int idx = lane + (i << 5);
        float dx = p[idx * 3 + 0] - qx;
        float dy = p[idx * 3 + 1] - qy;
        float dz = p[idx * 3 + 2] - qz;
        float d = dx * dx + dy * dy + dz * dz;
        if (d < worst) {
#pragma unroll
            for (int t = 0; t < 16; t++)
                if (t == wpos) { d16[t] = d; i16[t] = idx; }
            worst = d16[0]; wpos = 0;
#pragma unroll
            for (int t = 1; t < 16; t++)
                if (d16[t] > worst) { worst = d16[t]; wpos = t; }
        }
    }
#pragma unroll
    for (int t = 0; t < 16; t++) {
        sd[w][lane * 16 + t] = d16[t];
        si[w][lane * 16 + t] = i16[t];
    }
    __syncwarp();
    for (int r = 0; r < 16; r++) {
        float mv = FLT_MAX; int mp = 0;
#pragma unroll
        for (int t = 0; t < 16; t++) {
            float v = sd[w][lane * 16 + t];
            if (v < mv) { mv = v; mp = lane * 16 + t; }
        }
#pragma unroll
        for (int off = 16; off; off >>= 1) {
            float ov = __shfl_down_sync(0xffffffffu, mv, off);
            int   op = __shfl_down_sync(0xffffffffu, mp, off);
            if (ov < mv) { mv = ov; mp = op; }
        }
        mp = __shfl_sync(0xffffffffu, mp, 0);
        if (lane == 0) {
            knn[(size_t)g * 16 + r] = si[w][mp];
            sd[w][mp] = FLT_MAX;
        }
        __syncwarp();
    }
}

// ============================================================================
// 3) Build MLP input: x1[n][0:3] = xyz[nbr]-query, x1[n][3:128] = feat[nbr].
//    One warp per sample row (128 channels, 4 per lane).
// ============================================================================
__global__ __launch_bounds__(256, 1)
void build_kernel(const float* __restrict__ xyz, const float* __restrict__ feat,
                  const int* __restrict__ knn, const float* __restrict__ new_xyz,
                  float* __restrict__ x1) {
    int w = threadIdx.x >> 5, lane = threadIdx.x & 31;
    int n = blockIdx.x * 8 + w;   // 0..131071
    int g = n >> 4;               // query id
    int b = g >> 11;
    int idx = knn[n];
    const float* src = xyz + ((size_t)b * NPT + idx) * 3;
    const float* f   = feat + ((size_t)b * NPT + idx) * DFEAT;
    float* dst = x1 + (size_t)n * C0;
#pragma unroll
    for (int t = 0; t < 4; t++) {
        int c = lane + t * 32;
        float v;
        if (c < 3) v = src[c] - new_xyz[(size_t)g * 3 + c];
        else       v = f[c - 3];
        dst[c] = v;
    }
}

// ============================================================================
// 4) GEMM: Y[m][c] = sum_k A[m][k] * W[c][k] + bias later.  K = 128 fixed.
//    64(M) x 128(N) block tile, 256 threads, 4x8 register tile / thread.
// ============================================================================
__global__ __launch_bounds__(256, 2)
void gemm_kernel(const float* __restrict__ A, const float* __restrict__ W,
                 const float* __restrict__ bias, float* __restrict__ Y, int Nout) {
    const int K = 128;
    __shared__ float As[16][64];
    __shared__ float Ws[16][128];
    int m0 = blockIdx.x * 64;
    int c0 = blockIdx.y * 128;
    int tid = threadIdx.x;
    int tx = tid & 15, ty = tid >> 4;

    float acc[4][8];
#pragma unroll
    for (int i = 0; i < 4; i++)
#pragma unroll
        for (int j = 0; j < 8; j++) acc[i][j] = 0.0f;

    for (int k0 = 0; k0 < K; k0 += 16) {
        {
            int m = tid >> 2, kv = (tid & 3) * 4;
            float4 a = *(const float4*)&A[(size_t)(m0 + m) * K + k0 + kv];
            As[kv + 0][m] = a.x; As[kv + 1][m] = a.y;
            As[kv + 2][m] = a.z; As[kv + 3][m] = a.w;
        }
        {
            int kv = (tid & 3) * 4;
#pragma unroll
            for (int r = 0; r < 2; r++) {
                int c = (tid >> 2) + 64 * r;
                float4 wv = *(const float4*)&W[(size_t)(c0 + c) * K + k0 + kv];
                Ws[kv + 0][c] = wv.x; Ws[kv + 1][c] = wv.y;
                Ws[kv + 2][c] = wv.z; Ws[kv + 3][c] = wv.w;
            }
        }
        __syncthreads();
#pragma unroll
        for (int kk = 0; kk < 16; kk++) {
            float4 a  = *(const float4*)&As[kk][ty * 4];
            float4 b0 = *(const float4*)&Ws[kk][tx * 8];
            float4 b1 = *(const float4*)&Ws[kk][tx * 8 + 4];
            float av[4] = {a.x, a.y, a.z, a.w};
            float bv[8] = {b0.x, b0.y, b0.z, b0.w, b1.x, b1.y, b1.z, b1.w};
#pragma unroll
            for (int i = 0; i < 4; i++)
#pragma unroll
                for (int j = 0; j < 8; j++) acc[i][j] += av[i] * bv[j];
        }
        __syncthreads();
    }
#pragma unroll
    for (int i = 0; i < 4; i++) {
        size_t row = (size_t)(m0 + ty * 4 + i) * Nout + c0 + tx * 8;
#pragma unroll
        for (int j = 0; j < 8; j++)
            Y[row + j] = acc[i][j] + bias[c0 + tx * 8 + j];
    }
}

// ============================================================================
// 5) BN batch statistics: deterministic two-stage column reduction.
// ============================================================================
__global__ void stats_kernel(const float* __restrict__ Y, float* __restrict__ part, int C) {
    int c = threadIdx.x;              // blockDim = C
    const int ROWS = MROWS / 256;     // 512
    size_t base = (size_t)blockIdx.x * ROWS * C;
    float s = 0.0f, q = 0.0f;
    for (int r = 0; r < ROWS; r++) {
        float v = Y[base + (size_t)r * C + c];
        s += v;
        q += v * v;
    }
    part[blockIdx.x * C + c] = s;
    part[65536 + blockIdx.x * C + c] = q;
}

__global__ void finalize_kernel(const float* __restrict__ part,
                                const float* __restrict__ gamma,
                                const float* __restrict__ beta,
                                float* __restrict__ scale, float* __restrict__ bias, int C) {
    int c = threadIdx.x;
    float s = 0.0f, q = 0.0f;
    for (int blk = 0; blk < 256; blk++) {
        s += part[blk * C + c];
        q += part[65536 + blk * C + c];
    }
    const float inv = 1.0f / (float)MROWS;
    float m = s * inv;
    float v = q * inv - m * m;
    float sc = gamma[c] * rsqrtf(v + 1e-5f);
    scale[c] = sc;
    bias[c] = beta[c] - m * sc;
}

// ============================================================================
// 6) BN + ReLU elementwise (in place), C power of two.
// ============================================================================
__global__ void bnrelu_kernel(float* __restrict__ Y, const float* __restrict__ scale,
                              const float* __restrict__ bias, int Cmask) {
    size_t i = (size_t)blockIdx.x * 256 + threadIdx.x;
    int c = (int)(i & Cmask);
    float v = fmaf(Y[i], scale[c], bias[c]);
    Y[i] = fmaxf(v, 0.0f);
}

// ============================================================================
// 7) BN2 + ReLU + max over k + transpose-to-[B,S,C2] output.
// ============================================================================
__global__ __launch_bounds__(256, 4)
void maxpool_kernel(const float* __restrict__ Y2, const float* __restrict__ scale,
                    const float* __restrict__ bias, float* __restrict__ out) {
    int g = blockIdx.x;      // (b,s) 0..8191
    int c = threadIdx.x;     // channel 0..255
    float sc = scale[c], bi = bias[c];
    const float* p = Y2 + (size_t)g * KNN * C2 + c;
    float m = -FLT_MAX;
#pragma unroll
    for (int j = 0; j < KNN; j++) {
        float v = fmaf(p[(size_t)j * C2], sc, bi);
        v = fmaxf(v, 0.0f);
        m = fmaxf(m, v);
    }
    out[(size_t)g * C2 + c] = m;
}

// ============================================================================
extern "C" void kernel_launch(void* const* d_in, const int* in_sizes, int n_in,
                              void* d_out, int out_size) {
    const float* xyz    = (const float*)d_in[0];
    const float* feat   = (const float*)d_in[1];
    const float* W1     = (const float*)d_in[2];
    const float* b1     = (const float*)d_in[3];
    const float* gamma1 = (const float*)d_in[4];
    const float* beta1  = (const float*)d_in[5];
    const float* W2     = (const float*)d_in[6];
    const float* b2     = (const float*)d_in[7];
    const float* gamma2 = (const float*)d_in[8];
    const float* beta2  = (const float*)d_in[9];

    float* out = (float*)d_out;
    float* out_newxyz = out;                       // [B,S,3] = 24576 floats
    float* out_x      = out + (size_t)BATCH * SPT * 3;  // [B,S,C2]

    float *x1, *y1, *y2, *part, *scale, *bias;
    int *fpsi, *knni;
    cudaGetSymbolAddress((void**)&x1,    g_x1);
    cudaGetSymbolAddress((void**)&y1,    g_y1);
    cudaGetSymbolAddress((void**)&y2,    g_y2);
    cudaGetSymbolAddress((void**)&part,  g_part);
    cudaGetSymbolAddress((void**)&scale, g_scale);
    cudaGetSymbolAddress((void**)&bias,  g_bias);
    cudaGetSymbolAddress((void**)&fpsi,  g_fps);
    cudaGetSymbolAddress((void**)&knni,  g_knn);

    // 1. FPS (also writes new_xyz directly to output)
    fps_kernel<<<BATCH, 1024>>>(xyz, fpsi, out_newxyz);
    // 2. kNN
    knn_kernel<<<(BATCH * SPT) / 8, 256>>>(xyz, out_newxyz, knni);
    // 3. gather + concat
    build_kernel<<<MROWS / 8, 256>>>(xyz, feat, knni, out_newxyz, x1);
    // 4. conv1
    {
        dim3 grid(MROWS / 64, C1 / 128);
        gemm_kernel<<<grid, 256>>>(x1, W1, b1, y1, C1);
    }
    // 5. BN1 stats + apply + relu (in place on y1)
    stats_kernel<<<256, C1>>>(y1, part, C1);
    finalize_kernel<<<1, C1>>>(part, gamma1, beta1, scale, bias, C1);
    bnrelu_kernel<<<(unsigned)(((size_t)MROWS * C1) / 256), 256>>>(y1, scale, bias, C1 - 1);
    // 6. conv2
    {
        dim3 grid(MROWS / 64, C2 / 128);
        gemm_kernel<<<grid, 256>>>(y1, W2, b2, y2, C2);
    }
    // 7. BN2 stats + fused BN+relu+maxpool
    stats_kernel<<<256, C2>>>(y2, part, C2);
    finalize_kernel<<<1, C2>>>(part, gamma2, beta2, scale, bias, C2);
    maxpool_kernel<<<BATCH * SPT, C2>>>(y2, scale, bias, out_x);
}

// round 4
// speedup vs baseline: 1.5237x; 1.5237x over previous
#include <cuda_runtime.h>
#include <cuda_bf16.h>
#include <cstdint>
#include <float.h>

// Problem constants (shapes fixed by the dataset)
#define BATCH 4
#define NPT   16384
#define SPT   2048
#define KNN   16
#define DFEAT 125
#define C0    128
#define C1    128
#define C2    256
#define MROWS (BATCH * SPT * KNN)   // 131072 samples through the MLP

// FPS cluster config
#define FCTAS 8
#define FTHREADS 256
#define FPTS (NPT / FCTAS / FTHREADS)   // 8 points per thread

// ---------------- scratch (static device globals; no allocation allowed) ----
__device__ float g_x1[(size_t)MROWS * C0];     // gathered/concat input
__device__ float g_y1[(size_t)MROWS * C1];     // conv1 out -> bn1relu in place
__device__ float g_y2[(size_t)MROWS * C2];     // conv2 out
__device__ float g_part[2 * 256 * 256];        // partial sums: [sum | sumsq]
__device__ float g_scale[256];
__device__ float g_bias[256];
__device__ int   g_knn[BATCH * SPT * KNN];
__device__ float g_sx[BATCH * NPT];            // SoA xyz
__device__ float g_sy[BATCH * NPT];
__device__ float g_sz[BATCH * NPT];

// ---------------------------------------------------------------------------
// helpers: DSMEM addressing
// ---------------------------------------------------------------------------
__device__ __forceinline__ uint32_t smem_u32(const void* p) {
    return (uint32_t)__cvta_generic_to_shared(p);
}
__device__ __forceinline__ uint32_t mapa_u32(uint32_t addr, uint32_t rank) {
    uint32_t r;
    asm("mapa.shared::cluster.u32 %0, %1, %2;" : "=r"(r) : "r"(addr), "r"(rank));
    return r;
}
__device__ __forceinline__ void st_cluster_f2(uint32_t addr, float a, float b) {
    uint64_t v;
    asm("mov.b64 %0, {%1,%2};" : "=l"(v) : "f"(a), "f"(b));
    asm volatile("st.shared::cluster.b64 [%0], %1;" :: "r"(addr), "l"(v) : "memory");
}
__device__ __forceinline__ void st_cluster_f1(uint32_t addr, float a) {
    asm volatile("st.shared::cluster.b32 [%0], %1;" :: "r"(addr), "f"(a) : "memory");
}

// ============================================================================
// 0) AoS -> SoA transpose of xyz (coalesced via smem staging)
// ============================================================================
__global__ __launch_bounds__(256)
void soa_kernel(const float* __restrict__ xyz) {
    __shared__ float buf[768];
    int t = threadIdx.x;
    size_t base = (size_t)blockIdx.x * 768;
#pragma unroll
    for (int r = 0; r < 3; r++) buf[t + 256 * r] = xyz[base + t + 256 * r];
    __syncthreads();
    size_t o = (size_t)blockIdx.x * 256 + t;
    g_sx[o] = buf[t * 3 + 0];
    g_sy[o] = buf[t * 3 + 1];
    g_sz[o] = buf[t * 3 + 2];
}

// ============================================================================
// 1) Farthest point sampling: 8-CTA cluster per batch (32 SMs total).
//    Each thread owns 8 points in registers. Per iteration:
//      update dists -> per-thread argmax -> warp reduce (carrying coords)
//      -> block reduce -> DSMEM push candidate to all 8 CTAs (double-buffered)
//      -> barrier.cluster -> every CTA picks the global winner locally.
//    Must match jnp argmax semantics exactly:
//      - no FMA contraction: (dx*dx + dy*dy) + dz*dz with __f*_rn
//      - tie-break: max value, then smallest index
//      - emits the farthest index of the PREVIOUS step (selected[0] = 0)
// ============================================================================
__global__ __launch_bounds__(FTHREADS, 1) __cluster_dims__(FCTAS, 1, 1)
void fps_cluster_kernel(float* __restrict__ new_xyz) {
    int b = blockIdx.x / FCTAS;
    int rank = blockIdx.x % FCTAS;
    int t = threadIdx.x;
    int w = t >> 5, lane = t & 31;
    int base = rank * (NPT / FCTAS);       // this CTA's slice start
    const float* sx = g_sx + (size_t)b * NPT;
    const float* sy = g_sy + (size_t)b * NPT;
    const float* sz = g_sz + (size_t)b * NPT;

    float px[FPTS], py[FPTS], pz[FPTS], dist[FPTS];
#pragma unroll
    for (int j = 0; j < FPTS; j++) {
        int i = base + j * FTHREADS + t;
        px[j] = sx[i]; py[j] = sy[i]; pz[j] = sz[i];
        dist[j] = 1e10f;
    }

    __shared__ float s_rv[8], s_rx[8], s_ry[8], s_rz[8];
    __shared__ int   s_ri[8];
    // candidate slots, double buffered: [buf][rank] -> (v, idxbits), (x, y), z
    __shared__ float2 c_vi[2][FCTAS];
    __shared__ float2 c_xy[2][FCTAS];
    __shared__ float  c_z[2][FCTAS];

    // warp0 lanes 0..7: remote addresses of MY slot in peer CTA "lane"
    uint32_t p_vi = 0, p_xy = 0, p_z = 0;
    if (w == 0 && lane < FCTAS) {
        p_vi = mapa_u32(smem_u32(&c_vi[0][rank]), lane);
        p_xy = mapa_u32(smem_u32(&c_xy[0][rank]), lane);
        p_z  = mapa_u32(smem_u32(&c_z[0][rank]),  lane);
    }

    float curx = sx[0], cury = sy[0], curz = sz[0];   // first centroid = index 0
    float* out = new_xyz + (size_t)b * SPT * 3;

    for (int s = 0; s < SPT; s++) {
        if (rank == 0 && t == 0) {
            out[s * 3 + 0] = curx;
            out[s * 3 + 1] = cury;
            out[s * 3 + 2] = curz;
        }
        // ---- update + per-thread argmax (track j only) ----
        float best = -1.0f; int bj = 0;
#pragma unroll
        for (int j = 0; j < FPTS; j++) {
            float dx = px[j] - curx, dy = py[j] - cury, dz = pz[j] - curz;
            float d = __fadd_rn(__fadd_rn(__fmul_rn(dx, dx), __fmul_rn(dy, dy)),
                                __fmul_rn(dz, dz));
            float nd = fminf(dist[j], d);
            dist[j] = nd;
            bool bt = nd > best;            // strict: keeps smaller j (smaller idx)
            best = bt ? nd : best;
            bj = bt ? j : bj;
        }
        int bi = base + bj * FTHREADS + t;
        float bx = px[0], by = py[0], bz = pz[0];
#pragma unroll
        for (int j = 1; j < FPTS; j++) {
            bool e = (bj == j);
            bx = e ? px[j] : bx; by = e ? py[j] : by; bz = e ? pz[j] : bz;
        }
        // ---- warp reduce (max val, tie -> smaller idx), carrying coords ----
#pragma unroll
        for (int off = 16; off; off >>= 1) {
            float ov = __shfl_down_sync(0xffffffffu, best, off);
            int   oi = __shfl_down_sync(0xffffffffu, bi, off);
            float ox = __shfl_down_sync(0xffffffffu, bx, off);
            float oy = __shfl_down_sync(0xffffffffu, by, off);
            float oz = __shfl_down_sync(0xffffffffu, bz, off);
            bool take = (ov > best) || (ov == best && oi < bi);
            if (take) { best = ov; bi = oi; bx = ox; by = oy; bz = oz; }
        }
        if (lane == 0) {
            s_rv[w] = best; s_ri[w] = bi;
            s_rx[w] = bx; s_ry[w] = by; s_rz[w] = bz;
        }
        __syncthreads();
        // ---- warp0: block reduce + push CTA candidate to all 8 CTAs ----
        if (w == 0) {
            float v = (lane < 8) ? s_rv[lane] : -2.0f;
            int   ii = (lane < 8) ? s_ri[lane] : 0x7fffffff;
            float x = (lane < 8) ? s_rx[lane] : 0.0f;
            float y = (lane < 8) ? s_ry[lane] : 0.0f;
            float z = (lane < 8) ? s_rz[lane] : 0.0f;
#pragma unroll
            for (int off = 4; off; off >>= 1) {
                float ov = __shfl_down_sync(0xffffffffu, v, off);
                int   oi = __shfl_down_sync(0xffffffffu, ii, off);
                float ox = __shfl_down_sync(0xffffffffu, x, off);
                float oy = __shfl_down_sync(0xffffffffu, y, off);
                float oz = __shfl_down_sync(0xffffffffu, z, off);
                bool take = (ov > v) || (ov == v && oi < ii);
                if (take) { v = ov; ii = oi; x = ox; y = oy; z = oz; }
            }
            v  = __shfl_sync(0xffffffffu, v, 0);
            ii = __shfl_sync(0xffffffffu, ii, 0);
            x  = __shfl_sync(0xffffffffu, x, 0);
            y  = __shfl_sync(0xffffffffu, y, 0);
            z  = __shfl_sync(0xffffffffu, z, 0);
            if (lane < FCTAS) {
                uint32_t o8 = (s & 1) ? (uint32_t)(FCTAS * 8) : 0u;
                uint32_t o4 = (s & 1) ? (uint32_t)(FCTAS * 4) : 0u;
                st_cluster_f2(p_vi + o8, v, __int_as_float(ii));
                st_cluster_f2(p_xy + o8, x, y);
                st_cluster_f1(p_z + o4, z);
            }
        }
        asm volatile("barrier.cluster.arrive.aligned;" ::: "memory");
        asm volatile("barrier.cluster.wait.aligned;" ::: "memory");
        // ---- all threads: select global winner from the 8 candidates ----
        int bf = s & 1;
        float2 vi = c_vi[bf][0];
        float wv = vi.x; int wi = __float_as_int(vi.y);
        float2 xy = c_xy[bf][0];
        float wx = xy.x, wy = xy.y, wz = c_z[bf][0];
#pragma unroll
        for (int r = 1; r < FCTAS; r++) {
            float2 rv = c_vi[bf][r];
            float v = rv.x; int ii = __float_as_int(rv.y);
            bool take = (v > wv) || (v == wv && ii < wi);
            if (take) {
                wv = v; wi = ii;
                float2 rxy = c_xy[bf][r];
                wx = rxy.x; wy = rxy.y; wz = c_z[bf][r];
            }
        }
        curx = wx; cury = wy; curz = wz;
    }
}

// ============================================================================
// 2) kNN (k=16). One warp per query; SoA coalesced loads; each lane keeps a
//    register top-16 over 512 strided points, then 512 -> 16 selection via
//    shared memory. Only the SET of neighbors matters downstream.
// ============================================================================
__global__ __launch_bounds__(256)
void knn_kernel(const float* __restrict__ new_xyz, int* __restrict__ knn) {
    __shared__ float sd[8][512];
    __shared__ int   si[8][512];
    int w = threadIdx.x >> 5, lane = threadIdx.x & 31;
    int g = blockIdx.x * 8 + w;     // query id 0..8191
    int b = g >> 11;
    const float* sx = g_sx + (size_t)b * NPT;
    const float* sy = g_sy + (size_t)b * NPT;
    const float* sz = g_sz + (size_t)b * NPT;
    float qx = new_xyz[(size_t)g * 3 + 0];
    float qy = new_xyz[(size_t)g * 3 + 1];
    float qz = new_xyz[(size_t)g * 3 + 2];

    float d16[16]; int i16[16];
#pragma unroll
    for (int t = 0; t < 16; t++) { d16[t] = FLT_MAX; i16[t] = 0; }
    float worst = FLT_MAX; int wpos = 0;

    for (int i = 0; i < NPT / 32; i++) {
        int idx = lane + (i << 5);
        float dx = sx[idx] - qx;
        float dy = sy[idx] - qy;
        float dz = sz[idx] - qz;
        float d = dx * dx + dy * dy + dz * dz;
        if (d < worst) {
#pragma unroll
            for (int t = 0; t < 16; t++)
                if (t == wpos) { d16[t] = d; i16[t] = idx; }
            worst = d16[0]; wpos = 0;
#pragma unroll
            for (int t = 1; t < 16; t++)
                if (d16[t] > worst) { worst = d16[t]; wpos = t; }
        }
    }
#pragma unroll
    for (int t = 0; t < 16; t++) {
        sd[w][lane * 16 + t] = d16[t];
        si[w][lane * 16 + t] = i16[t];
    }
    __syncwarp();
    for (int r = 0; r < 16; r++) {
        float mv = FLT_MAX; int mp = 0;
#pragma unroll
        for (int t = 0; t < 16; t++) {
            float v = sd[w][lane * 16 + t];
            if (v < mv) { mv = v; mp = lane * 16 + t; }
        }
#pragma unroll
        for (int off = 16; off; off >>= 1) {
            float ov = __shfl_down_sync(0xffffffffu, mv, off);
            int   op = __shfl_down_sync(0xffffffffu, mp, off);
            if (ov < mv) { mv = ov; mp = op; }
        }
        mp = __shfl_sync(0xffffffffu, mp, 0);
        if (lane == 0) {
            knn[(size_t)g * 16 + r] = si[w][mp];
            sd[w][mp] = FLT_MAX;
        }
        __syncwarp();
    }
}

// ============================================================================
// 3) Build MLP input: x1[n][0:3] = xyz[nbr]-query, x1[n][3:128] = feat[nbr].
// ============================================================================
__global__ __launch_bounds__(256)
void build_kernel(const float* __restrict__ feat,
                  const int* __restrict__ knn, const float* __restrict__ new_xyz,
                  float* __restrict__ x1) {
    int w = threadIdx.x >> 5, lane = threadIdx.x & 31;
    int n = blockIdx.x * 8 + w;   // 0..131071
    int g = n >> 4;               // query id
    int b = g >> 11;
    int idx = knn[n];
    const float* f = feat + ((size_t)b * NPT + idx) * DFEAT;
    float* dst = x1 + (size_t)n * C0;
#pragma unroll
    for (int t = 0; t < 4; t++) {
        int c = lane + t * 32;
        float v;
        if (c == 0)      v = g_sx[(size_t)b * NPT + idx] - new_xyz[(size_t)g * 3 + 0];
        else if (c == 1) v = g_sy[(size_t)b * NPT + idx] - new_xyz[(size_t)g * 3 + 1];
        else if (c == 2) v = g_sz[(size_t)b * NPT + idx] - new_xyz[(size_t)g * 3 + 2];
        else             v = f[c - 3];
        dst[c] = v;
    }
}

// ============================================================================
// 4) GEMM: Y[m][c] = sum_k A[m][k] * W[c][k] (+bias). K = 128 fixed.
//    64(M) x 128(N) block tile, 256 threads, 4x8 register tile / thread.
// ============================================================================
__global__ __launch_bounds__(256, 2)
void gemm_kernel(const float* __restrict__ A, const float* __restrict__ W,
                 const float* __restrict__ bias, float* __restrict__ Y, int Nout) {
    const int K = 128;
    __shared__ float As[16][64];
    __shared__ float Ws[16][128];
    int m0 = blockIdx.x * 64;
    int c0 = blockIdx.y * 128;
    int tid = threadIdx.x;
    int tx = tid & 15, ty = tid >> 4;

    float acc[4][8];
#pragma unroll
    for (int i = 0; i < 4; i++)
#pragma unroll
        for (int j = 0; j < 8; j++) acc[i][j] = 0.0f;

    for (int k0 = 0; k0 < K; k0 += 16) {
        {
            int m = tid >> 2, kv = (tid & 3) * 4;
            float4 a = *(const float4*)&A[(size_t)(m0 + m) * K + k0 + kv];
            As[kv + 0][m] = a.x; As[kv + 1][m] = a.y;
            As[kv + 2][m] = a.z; As[kv + 3][m] = a.w;
        }
        {
            int kv = (tid & 3) * 4;
#pragma unroll
            for (int r = 0; r < 2; r++) {
                int c = (tid >> 2) + 64 * r;
                float4 wv = *(const float4*)&W[(size_t)(c0 + c) * K + k0 + kv];
                Ws[kv + 0][c] = wv.x; Ws[kv + 1][c] = wv.y;
                Ws[kv + 2][c] = wv.z; Ws[kv + 3][c] = wv.w;
            }
        }
        __syncthreads();
#pragma unroll
        for (int kk = 0; kk < 16; kk++) {
            float4 a  = *(const float4*)&As[kk][ty * 4];
            float4 b0 = *(const float4*)&Ws[kk][tx * 8];
            float4 b1 = *(const float4*)&Ws[kk][tx * 8 + 4];
            float av[4] = {a.x, a.y, a.z, a.w};
            float bv[8] = {b0.x, b0.y, b0.z, b0.w, b1.x, b1.y, b1.z, b1.w};
#pragma unroll
            for (int i = 0; i < 4; i++)
#pragma unroll
                for (int j = 0; j < 8; j++) acc[i][j] += av[i] * bv[j];
        }
        __syncthreads();
    }
#pragma unroll
    for (int i = 0; i < 4; i++) {
        size_t row = (size_t)(m0 + ty * 4 + i) * Nout + c0 + tx * 8;
#pragma unroll
        for (int j = 0; j < 8; j++)
            Y[row + j] = acc[i][j] + bias[c0 + tx * 8 + j];
    }
}

// ============================================================================
// 5) BN batch statistics: deterministic two-stage column reduction.
// ============================================================================
__global__ void stats_kernel(const float* __restrict__ Y, float* __restrict__ part, int C) {
    int c = threadIdx.x;              // blockDim = C
    const int ROWS = MROWS / 256;     // 512
    size_t base = (size_t)blockIdx.x * ROWS * C;
    float s = 0.0f, q = 0.0f;
    for (int r = 0; r < ROWS; r++) {
        float v = Y[base + (size_t)r * C + c];
        s += v;
        q += v * v;
    }
    part[blockIdx.x * C + c] = s;
    part[65536 + blockIdx.x * C + c] = q;
}

__global__ void finalize_kernel(const float* __restrict__ part,
                                const float* __restrict__ gamma,
                                const float* __restrict__ beta,
                                float* __restrict__ scale, float* __restrict__ bias, int C) {
    int c = threadIdx.x;
    float s = 0.0f, q = 0.0f;
    for (int blk = 0; blk < 256; blk++) {
        s += part[blk * C + c];
        q += part[65536 + blk * C + c];
    }
    const float inv = 1.0f / (float)MROWS;
    float m = s * inv;
    float v = q * inv - m * m;
    float sc = gamma[c] * rsqrtf(v + 1e-5f);
    scale[c] = sc;
    bias[c] = beta[c] - m * sc;
}

// ============================================================================
// 6) BN + ReLU elementwise (in place), C power of two.
// ============================================================================
__global__ void bnrelu_kernel(float* __restrict__ Y, const float* __restrict__ scale,
                              const float* __restrict__ bias, int Cmask) {
    size_t i = (size_t)blockIdx.x * 256 + threadIdx.x;
    int c = (int)(i & Cmask);
    float v = fmaf(Y[i], scale[c], bias[c]);
    Y[i] = fmaxf(v, 0.0f);
}

// ============================================================================
// 7) BN2 + ReLU + max over k + transpose-to-[B,S,C2] output.
// ============================================================================
__global__ __launch_bounds__(256, 4)
void maxpool_kernel(const float* __restrict__ Y2, const float* __restrict__ scale,
                    const float* __restrict__ bias, float* __restrict__ out) {
    int g = blockIdx.x;      // (b,s) 0..8191
    int c = threadIdx.x;     // channel 0..255
    float sc = scale[c], bi = bias[c];
    const float* p = Y2 + (size_t)g * KNN * C2 + c;
    float m = -FLT_MAX;
#pragma unroll
    for (int j = 0; j < KNN; j++) {
        float v = fmaf(p[(size_t)j * C2], sc, bi);
        v = fmaxf(v, 0.0f);
        m = fmaxf(m, v);
    }
    out[(size_t)g * C2 + c] = m;
}

// ============================================================================
extern "C" void kernel_launch(void* const* d_in, const int* in_sizes, int n_in,
                              void* d_out, int out_size) {
    const float* xyz    = (const float*)d_in[0];
    const float* feat   = (const float*)d_in[1];
    const float* W1     = (const float*)d_in[2];
    const float* b1     = (const float*)d_in[3];
    const float* gamma1 = (const float*)d_in[4];
    const float* beta1  = (const float*)d_in[5];
    const float* W2     = (const float*)d_in[6];
    const float* b2     = (const float*)d_in[7];
    const float* gamma2 = (const float*)d_in[8];
    const float* beta2  = (const float*)d_in[9];

    float* out = (float*)d_out;
    float* out_newxyz = out;                            // [B,S,3]
    float* out_x      = out + (size_t)BATCH * SPT * 3;  // [B,S,C2]

    float *x1, *y1, *y2, *part, *scale, *bias;
    int *knni;
    cudaGetSymbolAddress((void**)&x1,    g_x1);
    cudaGetSymbolAddress((void**)&y1,    g_y1);
    cudaGetSymbolAddress((void**)&y2,    g_y2);
    cudaGetSymbolAddress((void**)&part,  g_part);
    cudaGetSymbolAddress((void**)&scale, g_scale);
    cudaGetSymbolAddress((void**)&bias,  g_bias);
    cudaGetSymbolAddress((void**)&knni,  g_knn);

    // 0. SoA transpose of xyz
    soa_kernel<<<(BATCH * NPT) / 256, 256>>>(xyz);
    // 1. FPS (cluster kernel; writes new_xyz directly to output)
    fps_cluster_kernel<<<BATCH * FCTAS, FTHREADS>>>(out_newxyz);
    // 2. kNN
    knn_kernel<<<(BATCH * SPT) / 8, 256>>>(out_newxyz, knni);
    // 3. gather + concat
    build_kernel<<<MROWS / 8, 256>>>(feat, knni, out_newxyz, x1);
    // 4. conv1
    {
        dim3 grid(MROWS / 64, C1 / 128);
        gemm_kernel<<<grid, 256>>>(x1, W1, b1, y1, C1);
    }
    // 5. BN1 stats + apply + relu (in place on y1)
    stats_kernel<<<256, C1>>>(y1, part, C1);
    finalize_kernel<<<1, C1>>>(part, gamma1, beta1, scale, bias, C1);
    bnrelu_kernel<<<(unsigned)(((size_t)MROWS * C1) / 256), 256>>>(y1, scale, bias, C1 - 1);
    // 6. conv2
    {
        dim3 grid(MROWS / 64, C2 / 128);
        gemm_kernel<<<grid, 256>>>(y1, W2, b2, y2, C2);
    }
    // 7. BN2 stats + fused BN+relu+maxpool
    stats_kernel<<<256, C2>>>(y2, part, C2);
    finalize_kernel<<<1, C2>>>(part, gamma2, beta2, scale, bias, C2);
    maxpool_kernel<<<BATCH * SPT, C2>>>(y2, scale, bias, out_x);
}

// round 5
// speedup vs baseline: 1.8519x; 1.2154x over previous
#include <cuda_runtime.h>
#include <cuda_bf16.h>
#include <cstdint>
#include <float.h>

// Problem constants (shapes fixed by the dataset)
#define BATCH 4
#define NPT   16384
#define SPT   2048
#define KNN   16
#define DFEAT 125
#define C0    128
#define C1    128
#define C2    256
#define MROWS (BATCH * SPT * KNN)   // 131072 samples through the MLP

// FPS cluster config
#define FCTAS 8
#define FTHREADS 256
#define FPTS (NPT / FCTAS / FTHREADS)   // 8 points per thread
#define XTX (FCTAS * 24)                // tx bytes per exchange (8 sources x 24B)

// ---------------- scratch (static device globals; no allocation allowed) ----
__device__ float g_x1[(size_t)MROWS * C0];     // gathered/concat input
__device__ float g_y1[(size_t)MROWS * C1];     // conv1 out (raw, pre-BN)
__device__ float g_y2[(size_t)MROWS * C2];     // conv2 out
__device__ float g_part[2 * 256 * 256];        // partial sums: [sum | sumsq]
__device__ float g_scale[256];
__device__ float g_bias[256];
__device__ int   g_knn[BATCH * SPT * KNN];
__device__ float g_sx[BATCH * NPT];            // SoA xyz
__device__ float g_sy[BATCH * NPT];
__device__ float g_sz[BATCH * NPT];

// ---------------------------------------------------------------------------
// helpers: DSMEM / mbarrier
// ---------------------------------------------------------------------------
__device__ __forceinline__ uint32_t smem_u32(const void* p) {
    return (uint32_t)__cvta_generic_to_shared(p);
}
__device__ __forceinline__ uint32_t mapa_u32(uint32_t addr, uint32_t rank) {
    uint32_t r;
    asm("mapa.shared::cluster.u32 %0, %1, %2;" : "=r"(r) : "r"(addr), "r"(rank));
    return r;
}
// store 8B to peer SMEM + complete_tx(8) on peer mbarrier (one async op)
__device__ __forceinline__ void st_async_f2(uint32_t raddr, uint32_t rmbar, float a, float b) {
    uint64_t v;
    asm("mov.b64 %0, {%1,%2};" : "=l"(v) : "f"(a), "f"(b));
    asm volatile("st.async.shared::cluster.mbarrier::complete_tx::bytes.b64 [%0], %1, [%2];"
                 :: "r"(raddr), "l"(v), "r"(rmbar) : "memory");
}
__device__ __forceinline__ void mbar_inval(uint32_t a) {
    asm volatile("mbarrier.inval.shared.b64 [%0];" :: "r"(a) : "memory");
}
__device__ __forceinline__ void mbar_init(uint32_t a, uint32_t cnt) {
    asm volatile("mbarrier.init.shared.b64 [%0], %1;" :: "r"(a), "r"(cnt) : "memory");
}
__device__ __forceinline__ void mbar_arrive_expect(uint32_t a, uint32_t tx) {
    asm volatile("mbarrier.arrive.expect_tx.shared.b64 _, [%0], %1;"
                 :: "r"(a), "r"(tx) : "memory");
}
__device__ __forceinline__ void mbar_wait(uint32_t mbar, uint32_t parity) {
    asm volatile(
        "{\n\t.reg .pred P;\n\t"
        "WAIT_%=:\n\t"
        "mbarrier.try_wait.parity.acquire.cluster.shared::cta.b64 P, [%0], %1, 0x989680;\n\t"
        "@P bra.uni DONE_%=;\n\t"
        "bra.uni WAIT_%=;\n\t"
        "DONE_%=:\n\t}"
        :: "r"(mbar), "r"(parity) : "memory");
}

// ============================================================================
// 0) AoS -> SoA transpose of xyz (coalesced via smem staging)
// ============================================================================
__global__ __launch_bounds__(256)
void soa_kernel(const float* __restrict__ xyz) {
    __shared__ float buf[768];
    int t = threadIdx.x;
    size_t base = (size_t)blockIdx.x * 768;
#pragma unroll
    for (int r = 0; r < 3; r++) buf[t + 256 * r] = xyz[base + t + 256 * r];
    __syncthreads();
    size_t o = (size_t)blockIdx.x * 256 + t;
    g_sx[o] = buf[t * 3 + 0];
    g_sy[o] = buf[t * 3 + 1];
    g_sz[o] = buf[t * 3 + 2];
}

// ============================================================================
// 1) FPS: 8-CTA cluster per batch, mbarrier/st.async candidate exchange
//    (no barrier.cluster on the critical path). Exact jnp argmax semantics:
//    - no FMA contraction: (dx*dx + dy*dy) + dz*dz with __f*_rn
//    - tie-break: max value, then smallest global index
//    - emits the farthest index of the PREVIOUS step (selected[0] = 0)
//    Exchange e (e>=1) delivers winner e on mbar[e&1], parity (e>>1)&1
//    (a dummy completed phase 0 on mbar[0] makes the parity formula uniform).
// ============================================================================
__global__ __launch_bounds__(FTHREADS, 1) __cluster_dims__(FCTAS, 1, 1)
void fps_cluster_kernel(float* __restrict__ new_xyz) {
    int b = blockIdx.x / FCTAS;
    int rank = blockIdx.x % FCTAS;
    int t = threadIdx.x;
    int w = t >> 5, lane = t & 31;
    int base = rank * (NPT / FCTAS);
    const float* sx = g_sx + (size_t)b * NPT;
    const float* sy = g_sy + (size_t)b * NPT;
    const float* sz = g_sz + (size_t)b * NPT;

    float px[FPTS], py[FPTS], pz[FPTS], dist[FPTS];
#pragma unroll
    for (int j = 0; j < FPTS; j++) {
        int i = base + j * FTHREADS + t;
        px[j] = sx[i]; py[j] = sy[i]; pz[j] = sz[i];
        dist[j] = 1e10f;
    }

    // candidate slots: [stage][source rank][3 x 8B] = (val,idx)(x,y)(z,pad)
    __shared__ __align__(8) uint64_t c_slot[2][FCTAS][3];
    __shared__ __align__(8) uint64_t mbar[2];
    // per-warp winners
    __shared__ float s_wv[8], s_wx[8], s_wy[8], s_wz[8];
    __shared__ int   s_wi[8];

    uint32_t mb0 = smem_u32(&mbar[0]);
    uint32_t mb1 = smem_u32(&mbar[1]);

    if (t == 0) {
        mbar_inval(mb0); mbar_inval(mb1);
        mbar_init(mb0, 1); mbar_init(mb1, 1);
        mbar_arrive_expect(mb0, 0);     // dummy: complete phase 0 immediately
        mbar_arrive_expect(mb0, XTX);   // arm exchange 2 (phase 1)
        mbar_arrive_expect(mb1, XTX);   // arm exchange 1 (phase 0)
    }
    __syncthreads();
    // peers' mbarrier init must be visible before any st.async targets them
    asm volatile("barrier.cluster.arrive.aligned;" ::: "memory");
    asm volatile("barrier.cluster.wait.aligned;" ::: "memory");

    // remote addresses: my slot row in peer CTA 'lane', both stages + mbars
    uint32_t r_s0 = 0, r_s1 = 0, r_m0 = 0, r_m1 = 0;
    if (w == 0 && lane < FCTAS) {
        r_s0 = mapa_u32(smem_u32(&c_slot[0][rank][0]), lane);
        r_s1 = mapa_u32(smem_u32(&c_slot[1][rank][0]), lane);
        r_m0 = mapa_u32(mb0, lane);
        r_m1 = mapa_u32(mb1, lane);
    }

    float curx = sx[0], cury = sy[0], curz = sz[0];   // centroid 0 = point 0
    float* out = new_xyz + (size_t)b * SPT * 3;

    for (int s = 0; s < SPT; s++) {
        if (s > 0) {
            // ---- wait exchange s, pick global winner from 8 candidates ----
            uint32_t mb = (s & 1) ? mb1 : mb0;
            mbar_wait(mb, (unsigned)((s >> 1) & 1));
            int bf = s & 1;
            const float2* sl = (const float2*)&c_slot[bf][0][0];
            float2 vi = sl[0];
            float wv = vi.x; int wi = __float_as_int(vi.y);
            float2 xy = sl[1];
            float wx = xy.x, wy = xy.y, wz = ((const float2*)&c_slot[bf][0][2])->x;
#pragma unroll
            for (int r = 1; r < FCTAS; r++) {
                float2 rv = ((const float2*)&c_slot[bf][r][0])[0];
                float v = rv.x; int ii = __float_as_int(rv.y);
                bool take = (v > wv) || (v == wv && ii < wi);
                if (take) {
                    wv = v; wi = ii;
                    float2 rxy = ((const float2*)&c_slot[bf][r][1])[0];
                    wx = rxy.x; wy = rxy.y;
                    wz = ((const float2*)&c_slot[bf][r][2])->x;
                }
            }
            curx = wx; cury = wy; curz = wz;
            // re-arm this mbar for exchange s+2 (safe: peers' s+2 stores are
            // gated by our s+1 push, which happens after the block sync below)
            if (t == 0 && s + 2 < SPT) mbar_arrive_expect(mb, XTX);
        }
        if (rank == 0 && t == 0) {
            out[s * 3 + 0] = curx;
            out[s * 3 + 1] = cury;
            out[s * 3 + 2] = curz;
        }
        // ---- update dists + per-thread argmax (strict > keeps smaller idx) --
        float best = -1.0f; int bj = 0;
#pragma unroll
        for (int j = 0; j < FPTS; j++) {
            float dx = px[j] - curx, dy = py[j] - cury, dz = pz[j] - curz;
            float d = __fadd_rn(__fadd_rn(__fmul_rn(dx, dx), __fmul_rn(dy, dy)),
                                __fmul_rn(dz, dz));
            float nd = fminf(dist[j], d);
            dist[j] = nd;
            bool bt = nd > best;
            best = bt ? nd : best;
            bj = bt ? j : bj;
        }
        int bi = base + bj * FTHREADS + t;
        float bx = px[0], by = py[0], bz = pz[0];
#pragma unroll
        for (int j = 1; j < FPTS; j++) {
            bool e = (bj == j);
            bx = e ? px[j] : bx; by = e ? py[j] : by; bz = e ? pz[j] : bz;
        }
        // ---- warp argmax via REDUX (value bits max, then min index) ----
        unsigned vb = __float_as_uint(best);           // dist >= 0 -> monotone
        unsigned mv = __reduce_max_sync(0xffffffffu, vb);
        unsigned cnd = (vb == mv) ? (unsigned)bi : 0xffffffffu;
        unsigned mi = __reduce_min_sync(0xffffffffu, cnd);
        if ((unsigned)bi == mi) {       // unique winner thread of this warp
            s_wv[w] = best; s_wi[w] = (int)mi;
            s_wx[w] = bx; s_wy[w] = by; s_wz[w] = bz;
        }
        __syncthreads();
        // ---- warp0: block argmax over 8 warps + push candidate to peers ----
        if (w == 0 && s + 1 < SPT) {
            unsigned vb8  = (lane < 8) ? __float_as_uint(s_wv[lane]) : 0u;
            unsigned idx8 = (lane < 8) ? (unsigned)s_wi[lane] : 0xffffffffu;
            unsigned mv2 = __reduce_max_sync(0xffffffffu, vb8);
            unsigned c2 = (lane < 8 && vb8 == mv2) ? idx8 : 0xffffffffu;
            unsigned mi2 = __reduce_min_sync(0xffffffffu, c2);
            unsigned msk = __ballot_sync(0xffffffffu, lane < 8 && idx8 == mi2 && vb8 == mv2);
            int l = __ffs(msk) - 1;
            float v = s_wv[l], x = s_wx[l], y = s_wy[l], z = s_wz[l];
            if (lane < FCTAS) {
                int st = (s + 1) & 1;
                uint32_t rs = st ? r_s1 : r_s0;
                uint32_t rm = st ? r_m1 : r_m0;
                st_async_f2(rs +  0, rm, v, __int_as_float((int)mi2));
                st_async_f2(rs +  8, rm, x, y);
                st_async_f2(rs + 16, rm, z, 0.0f);
            }
        }
    }
    // keep SMEM alive until every CTA's last consumption is done
    asm volatile("barrier.cluster.arrive.aligned;" ::: "memory");
    asm volatile("barrier.cluster.wait.aligned;" ::: "memory");
}

// ============================================================================
// 2) kNN (k=16). One warp per query; SoA coalesced loads; register top-16
//    per lane over 512 points, then 512 -> 16 selection via shared memory.
//    Only the SET of neighbors matters downstream.
// ============================================================================
__global__ __launch_bounds__(256)
void knn_kernel(const float* __restrict__ new_xyz, int* __restrict__ knn) {
    __shared__ float sd[8][512];
    __shared__ int   si[8][512];
    int w = threadIdx.x >> 5, lane = threadIdx.x & 31;
    int g = blockIdx.x * 8 + w;     // query id 0..8191
    int b = g >> 11;
    const float* sx = g_sx + (size_t)b * NPT;
    const float* sy = g_sy + (size_t)b * NPT;
    const float* sz = g_sz + (size_t)b * NPT;
    float qx = new_xyz[(size_t)g * 3 + 0];
    float qy = new_xyz[(size_t)g * 3 + 1];
    float qz = new_xyz[(size_t)g * 3 + 2];

    float d16[16]; int i16[16];
#pragma unroll
    for (int t = 0; t < 16; t++) { d16[t] = FLT_MAX; i16[t] = 0; }
    float worst = FLT_MAX; int wpos = 0;

    for (int i = 0; i < NPT / 32; i++) {
        int idx = lane + (i << 5);
        float dx = sx[idx] - qx;
        float dy = sy[idx] - qy;
        float dz = sz[idx] - qz;
        float d = dx * dx + dy * dy + dz * dz;
        if (d < worst) {
#pragma unroll
            for (int t = 0; t < 16; t++)
                if (t == wpos) { d16[t] = d; i16[t] = idx; }
            worst = d16[0]; wpos = 0;
#pragma unroll
            for (int t = 1; t < 16; t++)
                if (d16[t] > worst) { worst = d16[t]; wpos = t; }
        }
    }
#pragma unroll
    for (int t = 0; t < 16; t++) {
        sd[w][lane * 16 + t] = d16[t];
        si[w][lane * 16 + t] = i16[t];
    }
    __syncwarp();
    for (int r = 0; r < 16; r++) {
        float mv = FLT_MAX; int mp = 0;
#pragma unroll
        for (int t = 0; t < 16; t++) {
            float v = sd[w][lane * 16 + t];
            if (v < mv) { mv = v; mp = lane * 16 + t; }
        }
#pragma unroll
        for (int off = 16; off; off >>= 1) {
            float ov = __shfl_down_sync(0xffffffffu, mv, off);
            int   op = __shfl_down_sync(0xffffffffu, mp, off);
            if (ov < mv) { mv = ov; mp = op; }
        }
        mp = __shfl_sync(0xffffffffu, mp, 0);
        if (lane == 0) {
            knn[(size_t)g * 16 + r] = si[w][mp];
            sd[w][mp] = FLT_MAX;
        }
        __syncwarp();
    }
}

// ============================================================================
// 3) Build MLP input: x1[n][0:3] = xyz[nbr]-query, x1[n][3:128] = feat[nbr].
// ============================================================================
__global__ __launch_bounds__(256)
void build_kernel(const float* __restrict__ feat,
                  const int* __restrict__ knn, const float* __restrict__ new_xyz,
                  float* __restrict__ x1) {
    int w = threadIdx.x >> 5, lane = threadIdx.x & 31;
    int n = blockIdx.x * 8 + w;   // 0..131071
    int g = n >> 4;               // query id
    int b = g >> 11;
    int idx = knn[n];
    const float* f = feat + ((size_t)b * NPT + idx) * DFEAT;
    float* dst = x1 + (size_t)n * C0;
#pragma unroll
    for (int t = 0; t < 4; t++) {
        int c = lane + t * 32;
        float v;
        if (c == 0)      v = g_sx[(size_t)b * NPT + idx] - new_xyz[(size_t)g * 3 + 0];
        else if (c == 1) v = g_sy[(size_t)b * NPT + idx] - new_xyz[(size_t)g * 3 + 1];
        else if (c == 2) v = g_sz[(size_t)b * NPT + idx] - new_xyz[(size_t)g * 3 + 2];
        else             v = f[c - 3];
        dst[c] = v;
    }
}

// ============================================================================
// 4) GEMM: Y[m][c] = sum_k A'[m][k] * W[c][k] + bias, K = 128 fixed.
//    Optional fused input transform: A' = relu(A*aScale[k] + aBias[k])
//    (folds BN1+ReLU of the previous layer into the A-tile load).
//    64(M) x 128(N) block tile, 256 threads, 4x8 register tile / thread.
// ============================================================================
__global__ __launch_bounds__(256, 2)
void gemm_kernel(const float* __restrict__ A, const float* __restrict__ W,
                 const float* __restrict__ bias, float* __restrict__ Y, int Nout,
                 const float* __restrict__ aScale, const float* __restrict__ aBias,
                 int fuseA) {
    const int K = 128;
    __shared__ float As[16][64];
    __shared__ float Ws[16][128];
    int m0 = blockIdx.x * 64;
    int c0 = blockIdx.y * 128;
    int tid = threadIdx.x;
    int tx = tid & 15, ty = tid >> 4;

    float acc[4][8];
#pragma unroll
    for (int i = 0; i < 4; i++)
#pragma unroll
        for (int j = 0; j < 8; j++) acc[i][j] = 0.0f;

    for (int k0 = 0; k0 < K; k0 += 16) {
        {
            int m = tid >> 2, kv = (tid & 3) * 4;
            float4 a = *(const float4*)&A[(size_t)(m0 + m) * K + k0 + kv];
            if (fuseA) {
                float4 sc = *(const float4*)&aScale[k0 + kv];
                float4 bi = *(const float4*)&aBias[k0 + kv];
                a.x = fmaxf(fmaf(a.x, sc.x, bi.x), 0.0f);
                a.y = fmaxf(fmaf(a.y, sc.y, bi.y), 0.0f);
                a.z = fmaxf(fmaf(a.z, sc.z, bi.z), 0.0f);
                a.w = fmaxf(fmaf(a.w, sc.w, bi.w), 0.0f);
            }
            As[kv + 0][m] = a.x; As[kv + 1][m] = a.y;
            As[kv + 2][m] = a.z; As[kv + 3][m] = a.w;
        }
        {
            int kv = (tid & 3) * 4;
#pragma unroll
            for (int r = 0; r < 2; r++) {
                int c = (tid >> 2) + 64 * r;
                float4 wv = *(const float4*)&W[(size_t)(c0 + c) * K + k0 + kv];
                Ws[kv + 0][c] = wv.x; Ws[kv + 1][c] = wv.y;
                Ws[kv + 2][c] = wv.z; Ws[kv + 3][c] = wv.w;
            }
        }
        __syncthreads();
#pragma unroll
        for (int kk = 0; kk < 16; kk++) {
            float4 a  = *(const float4*)&As[kk][ty * 4];
            float4 b0 = *(const float4*)&Ws[kk][tx * 8];
            float4 b1 = *(const float4*)&Ws[kk][tx * 8 + 4];
            float av[4] = {a.x, a.y, a.z, a.w};
            float bv[8] = {b0.x, b0.y, b0.z, b0.w, b1.x, b1.y, b1.z, b1.w};
#pragma unroll
            for (int i = 0; i < 4; i++)
#pragma unroll
                for (int j = 0; j < 8; j++) acc[i][j] += av[i] * bv[j];
        }
        __syncthreads();
    }
#pragma unroll
    for (int i = 0; i < 4; i++) {
        size_t row = (size_t)(m0 + ty * 4 + i) * Nout + c0 + tx * 8;
#pragma unroll
        for (int j = 0; j < 8; j++)
            Y[row + j] = acc[i][j] + bias[c0 + tx * 8 + j];
    }
}

// ============================================================================
// 5) BN batch statistics: deterministic two-stage column reduction.
// ============================================================================
__global__ void stats_kernel(const float* __restrict__ Y, float* __restrict__ part, int C) {
    int c = threadIdx.x;              // blockDim = C
    const int ROWS = MROWS / 256;     // 512
    size_t base = (size_t)blockIdx.x * ROWS * C;
    float s = 0.0f, q = 0.0f;
    for (int r = 0; r < ROWS; r++) {
        float v = Y[base + (size_t)r * C + c];
        s += v;
        q += v * v;
    }
    part[blockIdx.x * C + c] = s;
    part[65536 + blockIdx.x * C + c] = q;
}

__global__ void finalize_kernel(const float* __restrict__ part,
                                const float* __restrict__ gamma,
                                const float* __restrict__ beta,
                                float* __restrict__ scale, float* __restrict__ bias, int C) {
    int c = threadIdx.x;
    float s = 0.0f, q = 0.0f;
    for (int blk = 0; blk < 256; blk++) {
        s += part[blk * C + c];
        q += part[65536 + blk * C + c];
    }
    const float inv = 1.0f / (float)MROWS;
    float m = s * inv;
    float v = q * inv - m * m;
    float sc = gamma[c] * rsqrtf(v + 1e-5f);
    scale[c] = sc;
    bias[c] = beta[c] - m * sc;
}

// ============================================================================
// 7) BN2 + ReLU + max over k + transpose-to-[B,S,C2] output.
// ============================================================================
__global__ __launch_bounds__(256, 4)
void maxpool_kernel(const float* __restrict__ Y2, const float* __restrict__ scale,
                    const float* __restrict__ bias, float* __restrict__ out) {
    int g = blockIdx.x;      // (b,s) 0..8191
    int c = threadIdx.x;     // channel 0..255
    float sc = scale[c], bi = bias[c];
    const float* p = Y2 + (size_t)g * KNN * C2 + c;
    float m = -FLT_MAX;
#pragma unroll
    for (int j = 0; j < KNN; j++) {
        float v = fmaf(p[(size_t)j * C2], sc, bi);
        v = fmaxf(v, 0.0f);
        m = fmaxf(m, v);
    }
    out[(size_t)g * C2 + c] = m;
}

// ============================================================================
extern "C" void kernel_launch(void* const* d_in, const int* in_sizes, int n_in,
                              void* d_out, int out_size) {
    const float* xyz    = (const float*)d_in[0];
    const float* feat   = (const float*)d_in[1];
    const float* W1     = (const float*)d_in[2];
    const float* b1     = (const float*)d_in[3];
    const float* gamma1 = (const float*)d_in[4];
    const float* beta1  = (const float*)d_in[5];
    const float* W2     = (const float*)d_in[6];
    const float* b2     = (const float*)d_in[7];
    const float* gamma2 = (const float*)d_in[8];
    const float* beta2  = (const float*)d_in[9];

    float* out = (float*)d_out;
    float* out_newxyz = out;                            // [B,S,3]
    float* out_x      = out + (size_t)BATCH * SPT * 3;  // [B,S,C2]

    float *x1, *y1, *y2, *part, *scale, *bias;
    int *knni;
    cudaGetSymbolAddress((void**)&x1,    g_x1);
    cudaGetSymbolAddress((void**)&y1,    g_y1);
    cudaGetSymbolAddress((void**)&y2,    g_y2);
    cudaGetSymbolAddress((void**)&part,  g_part);
    cudaGetSymbolAddress((void**)&scale, g_scale);
    cudaGetSymbolAddress((void**)&bias,  g_bias);
    cudaGetSymbolAddress((void**)&knni,  g_knn);

    // 0. SoA transpose of xyz
    soa_kernel<<<(BATCH * NPT) / 256, 256>>>(xyz);
    // 1. FPS (cluster kernel; writes new_xyz directly to output)
    fps_cluster_kernel<<<BATCH * FCTAS, FTHREADS>>>(out_newxyz);
    // 2. kNN
    knn_kernel<<<(BATCH * SPT) / 8, 256>>>(out_newxyz, knni);
    // 3. gather + concat
    build_kernel<<<MROWS / 8, 256>>>(feat, knni, out_newxyz, x1);
    // 4. conv1 (raw output; BN1 applied later inside gemm2's A-load)
    {
        dim3 grid(MROWS / 64, C1 / 128);
        gemm_kernel<<<grid, 256>>>(x1, W1, b1, y1, C1, nullptr, nullptr, 0);
    }
    // 5. BN1 stats -> scale/bias
    stats_kernel<<<256, C1>>>(y1, part, C1);
    finalize_kernel<<<1, C1>>>(part, gamma1, beta1, scale, bias, C1);
    // 6. conv2 with fused BN1+ReLU on the A side
    {
        dim3 grid(MROWS / 64, C2 / 128);
        gemm_kernel<<<grid, 256>>>(y1, W2, b2, y2, C2, scale, bias, 1);
    }
    // 7. BN2 stats + fused BN+relu+maxpool
    stats_kernel<<<256, C2>>>(y2, part, C2);
    finalize_kernel<<<1, C2>>>(part, gamma2, beta2, scale, bias, C2);
    maxpool_kernel<<<BATCH * SPT, C2>>>(y2, scale, bias, out_x);
}

// round 6
// speedup vs baseline: 1.9372x; 1.0461x over previous
#include <cuda_runtime.h>
#include <cuda_bf16.h>
#include <cstdint>
#include <float.h>

// Problem constants (shapes fixed by the dataset)
#define BATCH 4
#define NPT   16384
#define SPT   2048
#define KNN   16
#define DFEAT 125
#define C0    128
#define C1    128
#define C2    256
#define MROWS (BATCH * SPT * KNN)   // 131072 samples through the MLP

// FPS cluster config: 4 CTAs x 512 threads per batch
#define FC 4
#define FT 512
#define FP (NPT / FC / FT)          // 8 points per thread
#define XT (FC * 8)                 // tx bytes per exchange (4 sources x 8B)
#define FPS_SMEM (3 * NPT * 4)      // full batch xyz in SMEM (192 KB)

// ---------------- scratch (static device globals; no allocation allowed) ----
__device__ float g_x1[(size_t)MROWS * C0];     // gathered/concat input
__device__ float g_y1[(size_t)MROWS * C1];     // conv1 out (raw, pre-BN)
__device__ float g_y2[(size_t)MROWS * C2];     // conv2 out
__device__ float g_max[(size_t)BATCH * SPT * C2]; // raw per-group max (8.4MB)
__device__ float g_part[2 * 256 * 256];        // partial sums: [sum | sumsq]
__device__ float g_scale[256];
__device__ float g_bias[256];
__device__ int   g_knn[BATCH * SPT * KNN];
__device__ float g_sx[BATCH * NPT];            // SoA xyz
__device__ float g_sy[BATCH * NPT];
__device__ float g_sz[BATCH * NPT];

// ---------------------------------------------------------------------------
// helpers: DSMEM / mbarrier
// ---------------------------------------------------------------------------
__device__ __forceinline__ uint32_t smem_u32(const void* p) {
    return (uint32_t)__cvta_generic_to_shared(p);
}
__device__ __forceinline__ uint32_t mapa_u32(uint32_t addr, uint32_t rank) {
    uint32_t r;
    asm("mapa.shared::cluster.u32 %0, %1, %2;" : "=r"(r) : "r"(addr), "r"(rank));
    return r;
}
// store 8B to peer SMEM + complete_tx(8) on peer mbarrier (one async op)
__device__ __forceinline__ void st_async_u64(uint32_t raddr, uint32_t rmbar, uint64_t v) {
    asm volatile("st.async.shared::cluster.mbarrier::complete_tx::bytes.b64 [%0], %1, [%2];"
                 :: "r"(raddr), "l"(v), "r"(rmbar) : "memory");
}
__device__ __forceinline__ void mbar_inval(uint32_t a) {
    asm volatile("mbarrier.inval.shared.b64 [%0];" :: "r"(a) : "memory");
}
__device__ __forceinline__ void mbar_init(uint32_t a, uint32_t cnt) {
    asm volatile("mbarrier.init.shared.b64 [%0], %1;" :: "r"(a), "r"(cnt) : "memory");
}
__device__ __forceinline__ void mbar_arrive_expect(uint32_t a, uint32_t tx) {
    asm volatile("mbarrier.arrive.expect_tx.shared.b64 _, [%0], %1;"
                 :: "r"(a), "r"(tx) : "memory");
}
__device__ __forceinline__ void mbar_wait(uint32_t mbar, uint32_t parity) {
    asm volatile(
        "{\n\t.reg .pred P;\n\t"
        "WAIT_%=:\n\t"
        "mbarrier.try_wait.parity.acquire.cluster.shared::cta.b64 P, [%0], %1, 0x989680;\n\t"
        "@P bra.uni DONE_%=;\n\t"
        "bra.uni WAIT_%=;\n\t"
        "DONE_%=:\n\t}"
        :: "r"(mbar), "r"(parity) : "memory");
}

// ============================================================================
// 0) AoS -> SoA transpose of xyz (coalesced via smem staging)
// ============================================================================
__global__ __launch_bounds__(256)
void soa_kernel(const float* __restrict__ xyz) {
    __shared__ float buf[768];
    int t = threadIdx.x;
    size_t base = (size_t)blockIdx.x * 768;
#pragma unroll
    for (int r = 0; r < 3; r++) buf[t + 256 * r] = xyz[base + t + 256 * r];
    __syncthreads();
    size_t o = (size_t)blockIdx.x * 256 + t;
    g_sx[o] = buf[t * 3 + 0];
    g_sy[o] = buf[t * 3 + 1];
    g_sz[o] = buf[t * 3 + 2];
}

// ============================================================================
// 1) FPS: 4-CTA x 512-thread cluster per batch. Single u64 candidate key
//    key = (dist_bits << 32) | ~idx  -> u64 max == (max dist, then min idx),
//    exactly jnp's argmax tie-break (dist >= 0 so bits are monotone).
//    One st.async per source CTA (4 mbarrier completions per exchange).
//    Full batch xyz lives in SMEM so winner-coordinate fetch is an LDS.
//    Exact jnp semantics preserved:
//      - no FMA contraction: (dx*dx + dy*dy) + dz*dz with __f*_rn
//      - emits the farthest index of the PREVIOUS step (selected[0] = 0)
//    Exchange e (e>=1) delivers winner e on mbar[e&1], parity (e>>1)&1
//    (dummy completed phase 0 on mbar[0] makes the parity formula uniform).
// ============================================================================
__global__ __launch_bounds__(FT, 1) __cluster_dims__(FC, 1, 1)
void fps_cluster_kernel(float* __restrict__ new_xyz) {
    extern __shared__ float smem[];
    float* shx = smem;
    float* shy = smem + NPT;
    float* shz = smem + 2 * NPT;

    int b = blockIdx.x / FC;
    int rank = blockIdx.x % FC;
    int t = threadIdx.x;
    int w = t >> 5, lane = t & 31;
    int base = rank * (NPT / FC);
    const float* sx = g_sx + (size_t)b * NPT;
    const float* sy = g_sy + (size_t)b * NPT;
    const float* sz = g_sz + (size_t)b * NPT;

    // stage full batch coords into SMEM (winner lookup = LDS broadcast)
    for (int i = t; i < NPT; i += FT) {
        shx[i] = sx[i]; shy[i] = sy[i]; shz[i] = sz[i];
    }

    // own slice in registers
    float px[FP], py[FP], pz[FP], dist[FP];
#pragma unroll
    for (int j = 0; j < FP; j++) {
        int i = base + j * FT + t;
        px[j] = sx[i]; py[j] = sy[i]; pz[j] = sz[i];
        dist[j] = 1e10f;
    }

    __shared__ __align__(8) uint64_t c_slot[2][FC];   // [stage][source rank]
    __shared__ __align__(8) uint64_t mbar[2];
    __shared__ __align__(8) uint64_t s_key[16];       // per-warp winners

    uint32_t mb0 = smem_u32(&mbar[0]);
    uint32_t mb1 = smem_u32(&mbar[1]);

    if (t == 0) {
        mbar_inval(mb0); mbar_inval(mb1);
        mbar_init(mb0, 1); mbar_init(mb1, 1);
        mbar_arrive_expect(mb0, 0);    // dummy: complete phase 0 immediately
        mbar_arrive_expect(mb0, XT);   // arm exchange 2 (phase 1)
        mbar_arrive_expect(mb1, XT);   // arm exchange 1 (phase 0)
    }
    __syncthreads();
    // peers' mbarrier init must be visible before any st.async targets them
    asm volatile("barrier.cluster.arrive.aligned;" ::: "memory");
    asm volatile("barrier.cluster.wait.aligned;" ::: "memory");

    // remote addresses: my slot in peer CTA 'lane', both stages + mbars
    uint32_t r_s0 = 0, r_s1 = 0, r_m0 = 0, r_m1 = 0;
    if (w == 0 && lane < FC) {
        r_s0 = mapa_u32(smem_u32(&c_slot[0][rank]), lane);
        r_s1 = mapa_u32(smem_u32(&c_slot[1][rank]), lane);
        r_m0 = mapa_u32(mb0, lane);
        r_m1 = mapa_u32(mb1, lane);
    }

    float curx = shx[0], cury = shy[0], curz = shz[0];   // centroid 0 = point 0
    float* out = new_xyz + (size_t)b * SPT * 3;

    for (int s = 0; s < SPT; s++) {
        if (s > 0) {
            // ---- wait exchange s, pick global winner from 4 u64 keys ----
            uint32_t mb = (s & 1) ? mb1 : mb0;
            mbar_wait(mb, (unsigned)((s >> 1) & 1));
            int bf = s & 1;
            uint64_t wk = c_slot[bf][0];
#pragma unroll
            for (int r = 1; r < FC; r++) {
                uint64_t k = c_slot[bf][r];
                wk = (k > wk) ? k : wk;
            }
            int wi = (int)(~(uint32_t)wk);
            curx = shx[wi]; cury = shy[wi]; curz = shz[wi];
            // re-arm this mbar for exchange s+2 (safe: peers' s+2 stores are
            // gated by our s+1 push, which happens after the sync below)
            if (t == 0 && s + 2 < SPT) mbar_arrive_expect(mb, XT);
        }
        if (rank == 0 && t == 0) {
            out[s * 3 + 0] = curx;
            out[s * 3 + 1] = cury;
            out[s * 3 + 2] = curz;
        }
        // ---- update dists + per-thread argmax (strict > keeps smaller idx) --
        float best = -1.0f; int bj = 0;
#pragma unroll
        for (int j = 0; j < FP; j++) {
            float dx = px[j] - curx, dy = py[j] - cury, dz = pz[j] - curz;
            float d = __fadd_rn(__fadd_rn(__fmul_rn(dx, dx), __fmul_rn(dy, dy)),
                                __fmul_rn(dz, dz));
            float nd = fminf(dist[j], d);
            dist[j] = nd;
            bool bt = nd > best;
            best = bt ? nd : best;
            bj = bt ? j : bj;
        }
        unsigned bi = (unsigned)(base + bj * FT + t);
        unsigned vb = __float_as_uint(best);     // dist >= 0 -> monotone bits
        // ---- warp argmax via REDUX: max value bits, then min index ----
        unsigned mv = __reduce_max_sync(0xffffffffu, vb);
        unsigned cnd = (vb == mv) ? ~bi : 0u;    // ~idx: bigger = smaller idx
        unsigned ml = __reduce_max_sync(0xffffffffu, cnd);
        if (lane == 0) s_key[w] = ((uint64_t)mv << 32) | ml;   // uniform value
        __syncthreads();
        // ---- warp0: block argmax over 16 warps + push key to 4 peers ----
        if (w == 0 && s + 1 < SPT) {
            unsigned hi = (lane < 16) ? (unsigned)(s_key[lane] >> 32) : 0u;
            unsigned lo = (lane < 16) ? (unsigned)s_key[lane] : 0u;
            unsigned mv2 = __reduce_max_sync(0xffffffffu, hi);
            unsigned c2 = (hi == mv2) ? lo : 0u;
            unsigned ml2 = __reduce_max_sync(0xffffffffu, c2);
            if (lane < FC) {
                int st = (s + 1) & 1;
                uint32_t rs = st ? r_s1 : r_s0;
                uint32_t rm = st ? r_m1 : r_m0;
                st_async_u64(rs, rm, ((uint64_t)mv2 << 32) | ml2);
            }
        }
    }
    // keep SMEM alive until every CTA's last consumption is done
    asm volatile("barrier.cluster.arrive.aligned;" ::: "memory");
    asm volatile("barrier.cluster.wait.aligned;" ::: "memory");
}

// ============================================================================
// 2) kNN (k=16). One warp per query; SoA coalesced loads; register top-16
//    per lane over 512 points, then 512 -> 16 selection via shared memory.
//    Only the SET of neighbors matters downstream.
// ============================================================================
__global__ __launch_bounds__(256)
void knn_kernel(const float* __restrict__ new_xyz, int* __restrict__ knn) {
    __shared__ float sd[8][512];
    __shared__ int   si[8][512];
    int w = threadIdx.x >> 5, lane = threadIdx.x & 31;
    int g = blockIdx.x * 8 + w;     // query id 0..8191
    int b = g >> 11;
    const float* sx = g_sx + (size_t)b * NPT;
    const float* sy = g_sy + (size_t)b * NPT;
    const float* sz = g_sz + (size_t)b * NPT;
    float qx = new_xyz[(size_t)g * 3 + 0];
    float qy = new_xyz[(size_t)g * 3 + 1];
    float qz = new_xyz[(size_t)g * 3 + 2];

    float d16[16]; int i16[16];
#pragma unroll
    for (int t = 0; t < 16; t++) { d16[t] = FLT_MAX; i16[t] = 0; }
    float worst = FLT_MAX; int wpos = 0;

    for (int i = 0; i < NPT / 32; i++) {
        int idx = lane + (i << 5);
        float dx = sx[idx] - qx;
        float dy = sy[idx] - qy;
        float dz = sz[idx] - qz;
        float d = dx * dx + dy * dy + dz * dz;
        if (d < worst) {
#pragma unroll
            for (int t = 0; t < 16; t++)
                if (t == wpos) { d16[t] = d; i16[t] = idx; }
            worst = d16[0]; wpos = 0;
#pragma unroll
            for (int t = 1; t < 16; t++)
                if (d16[t] > worst) { worst = d16[t]; wpos = t; }
        }
    }
#pragma unroll
    for (int t = 0; t < 16; t++) {
        sd[w][lane * 16 + t] = d16[t];
        si[w][lane * 16 + t] = i16[t];
    }
    __syncwarp();
    for (int r = 0; r < 16; r++) {
        float mv = FLT_MAX; int mp = 0;
#pragma unroll
        for (int t = 0; t < 16; t++) {
            float v = sd[w][lane * 16 + t];
            if (v < mv) { mv = v; mp = lane * 16 + t; }
        }
#pragma unroll
        for (int off = 16; off; off >>= 1) {
            float ov = __shfl_down_sync(0xffffffffu, mv, off);
            int   op = __shfl_down_sync(0xffffffffu, mp, off);
            if (ov < mv) { mv = ov; mp = op; }
        }
        mp = __shfl_sync(0xffffffffu, mp, 0);
        if (lane == 0) {
            knn[(size_t)g * 16 + r] = si[w][mp];
            sd[w][mp] = FLT_MAX;
        }
        __syncwarp();
    }
}

// ============================================================================
// 3) Build MLP input: x1[n][0:3] = xyz[nbr]-query, x1[n][3:128] = feat[nbr].
// ============================================================================
__global__ __launch_bounds__(256)
void build_kernel(const float* __restrict__ feat,
                  const int* __restrict__ knn, const float* __restrict__ new_xyz,
                  float* __restrict__ x1) {
    int w = threadIdx.x >> 5, lane = threadIdx.x & 31;
    int n = blockIdx.x * 8 + w;   // 0..131071
    int g = n >> 4;               // query id
    int b = g >> 11;
    int idx = knn[n];
    const float* f = feat + ((size_t)b * NPT + idx) * DFEAT;
    float* dst = x1 + (size_t)n * C0;
#pragma unroll
    for (int t = 0; t < 4; t++) {
        int c = lane + t * 32;
        float v;
        if (c == 0)      v = g_sx[(size_t)b * NPT + idx] - new_xyz[(size_t)g * 3 + 0];
        else if (c == 1) v = g_sy[(size_t)b * NPT + idx] - new_xyz[(size_t)g * 3 + 1];
        else if (c == 2) v = g_sz[(size_t)b * NPT + idx] - new_xyz[(size_t)g * 3 + 2];
        else             v = f[c - 3];
        dst[c] = v;
    }
}

// ============================================================================
// 4) GEMM: Y[m][c] = sum_k A'[m][k] * W[c][k] + bias, K = 128 fixed.
//    Optional fused input transform: A' = relu(A*aScale[k] + aBias[k]).
//    Optional fused epilogue: raw max over each group of 16 rows -> gmax
//    (BN2+ReLU applied later; valid since BN scale > 0 makes it monotone).
//    64(M) x 128(N) block tile, 256 threads, 4x8 register tile / thread.
// ============================================================================
__global__ __launch_bounds__(256, 2)
void gemm_kernel(const float* __restrict__ A, const float* __restrict__ W,
                 const float* __restrict__ bias, float* __restrict__ Y, int Nout,
                 const float* __restrict__ aScale, const float* __restrict__ aBias,
                 int fuseA, float* __restrict__ gmax, int fuseMax) {
    const int K = 128;
    __shared__ float As[16][64];
    __shared__ float Ws[16][128];
    __shared__ float redm[16][128];
    int m0 = blockIdx.x * 64;
    int c0 = blockIdx.y * 128;
    int tid = threadIdx.x;
    int tx = tid & 15, ty = tid >> 4;

    float acc[4][8];
#pragma unroll
    for (int i = 0; i < 4; i++)
#pragma unroll
        for (int j = 0; j < 8; j++) acc[i][j] = 0.0f;

    for (int k0 = 0; k0 < K; k0 += 16) {
        {
            int m = tid >> 2, kv = (tid & 3) * 4;
            float4 a = *(const float4*)&A[(size_t)(m0 + m) * K + k0 + kv];
            if (fuseA) {
                float4 sc = *(const float4*)&aScale[k0 + kv];
                float4 bi = *(const float4*)&aBias[k0 + kv];
                a.x = fmaxf(fmaf(a.x, sc.x, bi.x), 0.0f);
                a.y = fmaxf(fmaf(a.y, sc.y, bi.y), 0.0f);
                a.z = fmaxf(fmaf(a.z, sc.z, bi.z), 0.0f);
                a.w = fmaxf(fmaf(a.w, sc.w, bi.w), 0.0f);
            }
            As[kv + 0][m] = a.x; As[kv + 1][m] = a.y;
            As[kv + 2][m] = a.z; As[kv + 3][m] = a.w;
        }
        {
            int kv = (tid & 3) * 4;
#pragma unroll
            for (int r = 0; r < 2; r++) {
                int c = (tid >> 2) + 64 * r;
                float4 wv = *(const float4*)&W[(size_t)(c0 + c) * K + k0 + kv];
                Ws[kv + 0][c] = wv.x; Ws[kv + 1][c] = wv.y;
                Ws[kv + 2][c] = wv.z; Ws[kv + 3][c] = wv.w;
            }
        }
        __syncthreads();
#pragma unroll
        for (int kk = 0; kk < 16; kk++) {
            float4 a  = *(const float4*)&As[kk][ty * 4];
            float4 b0 = *(const float4*)&Ws[kk][tx * 8];
            float4 b1 = *(const float4*)&Ws[kk][tx * 8 + 4];
            float av[4] = {a.x, a.y, a.z, a.w};
            float bv[8] = {b0.x, b0.y, b0.z, b0.w, b1.x, b1.y, b1.z, b1.w};
#pragma unroll
            for (int i = 0; i < 4; i++)
#pragma unroll
                for (int j = 0; j < 8; j++) acc[i][j] += av[i] * bv[j];
        }
        __syncthreads();
    }
#pragma unroll
    for (int i = 0; i < 4; i++) {
        size_t row = (size_t)(m0 + ty * 4 + i) * Nout + c0 + tx * 8;
#pragma unroll
        for (int j = 0; j < 8; j++) {
            acc[i][j] += bias[c0 + tx * 8 + j];
            Y[row + j] = acc[i][j];
        }
    }
    if (fuseMax) {
        // each thread's 4 rows lie in one group of 16 (group-local id ty/4)
#pragma unroll
        for (int j = 0; j < 8; j++) {
            float m = fmaxf(fmaxf(acc[0][j], acc[1][j]), fmaxf(acc[2][j], acc[3][j]));
            redm[ty][tx * 8 + j] = m;
        }
        __syncthreads();
        if (ty < 4) {   // ty = group 0..3 within this 64-row tile
#pragma unroll
            for (int j = 0; j < 8; j++) {
                int c = tx * 8 + j;
                float m = fmaxf(fmaxf(redm[ty * 4 + 0][c], redm[ty * 4 + 1][c]),
                                fmaxf(redm[ty * 4 + 2][c], redm[ty * 4 + 3][c]));
                gmax[(size_t)(m0 / 16 + ty) * Nout + c0 + c] = m;
            }
        }
    }
}

// ============================================================================
// 5) BN batch statistics: deterministic two-stage column reduction.
// ============================================================================
__global__ void stats_kernel(const float* __restrict__ Y, float* __restrict__ part, int C) {
    int c = threadIdx.x;              // blockDim = C
    const int ROWS = MROWS / 256;     // 512
    size_t base = (size_t)blockIdx.x * ROWS * C;
    float s = 0.0f, q = 0.0f;
    for (int r = 0; r < ROWS; r++) {
        float v = Y[base + (size_t)r * C + c];
        s += v;
        q += v * v;
    }
    part[blockIdx.x * C + c] = s;
    part[65536 + blockIdx.x * C + c] = q;
}

__global__ void finalize_kernel(const float* __restrict__ part,
                                const float* __restrict__ gamma,
                                const float* __restrict__ beta,
                                float* __restrict__ scale, float* __restrict__ bias, int C) {
    int c = threadIdx.x;
    float s = 0.0f, q = 0.0f;
    for (int blk = 0; blk < 256; blk++) {
        s += part[blk * C + c];
        q += part[65536 + blk * C + c];
    }
    const float inv = 1.0f / (float)MROWS;
    float m = s * inv;
    float v = q * inv - m * m;
    float sc = gamma[c] * rsqrtf(v + 1e-5f);
    scale[c] = sc;
    bias[c] = beta[c] - m * sc;
}

// ============================================================================
// 7) BN2 + ReLU on the pre-reduced group max (monotone: scale > 0).
// ============================================================================
__global__ __launch_bounds__(256, 4)
void maxpool_kernel(const float* __restrict__ gmax, const float* __restrict__ scale,
                    const float* __restrict__ bias, float* __restrict__ out) {
    int g = blockIdx.x;      // (b,s) 0..8191
    int c = threadIdx.x;     // channel 0..255
    float v = fmaf(gmax[(size_t)g * C2 + c], scale[c], bias[c]);
    out[(size_t)g * C2 + c] = fmaxf(v, 0.0f);
}

// ============================================================================
extern "C" void kernel_launch(void* const* d_in, const int* in_sizes, int n_in,
                              void* d_out, int out_size) {
    const float* xyz    = (const float*)d_in[0];
    const float* feat   = (const float*)d_in[1];
    const float* W1     = (const float*)d_in[2];
    const float* b1     = (const float*)d_in[3];
    const float* gamma1 = (const float*)d_in[4];
    const float* beta1  = (const float*)d_in[5];
    const float* W2     = (const float*)d_in[6];
    const float* b2     = (const float*)d_in[7];
    const float* gamma2 = (const float*)d_in[8];
    const float* beta2  = (const float*)d_in[9];

    float* out = (float*)d_out;
    float* out_newxyz = out;                            // [B,S,3]
    float* out_x      = out + (size_t)BATCH * SPT * 3;  // [B,S,C2]

    float *x1, *y1, *y2, *gmax, *part, *scale, *bias;
    int *knni;
    cudaGetSymbolAddress((void**)&x1,    g_x1);
    cudaGetSymbolAddress((void**)&y1,    g_y1);
    cudaGetSymbolAddress((void**)&y2,    g_y2);
    cudaGetSymbolAddress((void**)&gmax,  g_max);
    cudaGetSymbolAddress((void**)&part,  g_part);
    cudaGetSymbolAddress((void**)&scale, g_scale);
    cudaGetSymbolAddress((void**)&bias,  g_bias);
    cudaGetSymbolAddress((void**)&knni,  g_knn);

    // 0. SoA transpose of xyz
    soa_kernel<<<(BATCH * NPT) / 256, 256>>>(xyz);
    // 1. FPS (cluster kernel; writes new_xyz directly to output)
    cudaFuncSetAttribute(fps_cluster_kernel,
                         cudaFuncAttributeMaxDynamicSharedMemorySize, FPS_SMEM);
    fps_cluster_kernel<<<BATCH * FC, FT, FPS_SMEM>>>(out_newxyz);
    // 2. kNN
    knn_kernel<<<(BATCH * SPT) / 8, 256>>>(out_newxyz, knni);
    // 3. gather + concat
    build_kernel<<<MROWS / 8, 256>>>(feat, knni, out_newxyz, x1);
    // 4. conv1 (raw output; BN1 applied later inside gemm2's A-load)
    {
        dim3 grid(MROWS / 64, C1 / 128);
        gemm_kernel<<<grid, 256>>>(x1, W1, b1, y1, C1, nullptr, nullptr, 0, nullptr, 0);
    }
    // 5. BN1 stats -> scale/bias
    stats_kernel<<<256, C1>>>(y1, part, C1);
    finalize_kernel<<<1, C1>>>(part, gamma1, beta1, scale, bias, C1);
    // 6. conv2 with fused BN1+ReLU on the A side and fused group-max epilogue
    {
        dim3 grid(MROWS / 64, C2 / 128);
        gemm_kernel<<<grid, 256>>>(y1, W2, b2, y2, C2, scale, bias, 1, gmax, 1);
    }
    // 7. BN2 stats + BN+relu on the pre-reduced max
    stats_kernel<<<256, C2>>>(y2, part, C2);
    finalize_kernel<<<1, C2>>>(part, gamma2, beta2, scale, bias, C2);
    maxpool_kernel<<<BATCH * SPT, C2>>>(gmax, scale, bias, out_x);
}

// round 8
// speedup vs baseline: 2.2904x; 1.1823x over previous
#include <cuda_runtime.h>
#include <cuda_bf16.h>
#include <cstdint>
#include <float.h>

// Problem constants (shapes fixed by the dataset)
#define BATCH 4
#define NPT   16384
#define SPT   2048
#define KNN   16
#define DFEAT 125
#define C0    128
#define C1    128
#define C2    256
#define MROWS (BATCH * SPT * KNN)   // 131072 samples through the MLP
#define MBLK  (MROWS / 64)          // 2048 gemm m-blocks
#define PSQ_OFF (MBLK * 256)        // sumsq offset inside g_part
#define RSQ_OFF (32 * 256)          // sumsq offset inside g_red

// FPS cluster config: 8 CTAs x 256 threads per batch
#define FC 8
#define FT 256
#define FP (NPT / FC / FT)          // 8 points per thread
#define XT (FC * 8)                 // tx bytes per exchange (8 sources x 8B)
#define FPS_SMEM (3 * NPT * 4)      // full batch xyz in SMEM (192 KB)

// ---------------- scratch (static device globals; no allocation allowed) ----
__device__ float g_x1[(size_t)MROWS * C0];     // gathered/concat input
__device__ float g_y1[(size_t)MROWS * C1];     // conv1 out (raw, pre-BN)
__device__ float g_max[(size_t)BATCH * SPT * C2]; // raw per-group max (8.4MB)
__device__ float g_part[2 * MBLK * 256];       // per-mblock [sum | sumsq]
__device__ float g_red[2 * 32 * 256];          // stage-1 reduced partials
__device__ float g_scale[256];
__device__ float g_bias[256];
__device__ int   g_knn[BATCH * SPT * KNN];
__device__ float g_sx[BATCH * NPT];            // SoA xyz
__device__ float g_sy[BATCH * NPT];
__device__ float g_sz[BATCH * NPT];

// ---------------------------------------------------------------------------
// helpers: DSMEM / mbarrier
// ---------------------------------------------------------------------------
__device__ __forceinline__ uint32_t smem_u32(const void* p) {
    return (uint32_t)__cvta_generic_to_shared(p);
}
__device__ __forceinline__ uint32_t mapa_u32(uint32_t addr, uint32_t rank) {
    uint32_t r;
    asm("mapa.shared::cluster.u32 %0, %1, %2;" : "=r"(r) : "r"(addr), "r"(rank));
    return r;
}
__device__ __forceinline__ void st_async_u64(uint32_t raddr, uint32_t rmbar, uint64_t v) {
    asm volatile("st.async.shared::cluster.mbarrier::complete_tx::bytes.b64 [%0], %1, [%2];"
                 :: "r"(raddr), "l"(v), "r"(rmbar) : "memory");
}
__device__ __forceinline__ void mbar_inval(uint32_t a) {
    asm volatile("mbarrier.inval.shared.b64 [%0];" :: "r"(a) : "memory");
}
__device__ __forceinline__ void mbar_init(uint32_t a, uint32_t cnt) {
    asm volatile("mbarrier.init.shared.b64 [%0], %1;" :: "r"(a), "r"(cnt) : "memory");
}
__device__ __forceinline__ void mbar_arrive_expect(uint32_t a, uint32_t tx) {
    asm volatile("mbarrier.arrive.expect_tx.shared.b64 _, [%0], %1;"
                 :: "r"(a), "r"(tx) : "memory");
}
__device__ __forceinline__ void mbar_wait(uint32_t mbar, uint32_t parity) {
    asm volatile(
        "{\n\t.reg .pred P;\n\t"
        "WAIT_%=:\n\t"
        "mbarrier.try_wait.parity.acquire.cluster.shared::cta.b64 P, [%0], %1, 0x989680;\n\t"
        "@P bra.uni DONE_%=;\n\t"
        "bra.uni WAIT_%=;\n\t"
        "DONE_%=:\n\t}"
        :: "r"(mbar), "r"(parity) : "memory");
}

// ============================================================================
// 0) AoS -> SoA transpose of xyz (coalesced via smem staging)
// ============================================================================
__global__ __launch_bounds__(256)
void soa_kernel(const float* __restrict__ xyz) {
    __shared__ float buf[768];
    int t = threadIdx.x;
    size_t base = (size_t)blockIdx.x * 768;
#pragma unroll
    for (int r = 0; r < 3; r++) buf[t + 256 * r] = xyz[base + t + 256 * r];
    __syncthreads();
    size_t o = (size_t)blockIdx.x * 256 + t;
    g_sx[o] = buf[t * 3 + 0];
    g_sy[o] = buf[t * 3 + 1];
    g_sz[o] = buf[t * 3 + 2];
}

// ============================================================================
// 1) FPS: 8-CTA x 256-thread cluster per batch. Single u64 candidate key
//    key = (dist_bits << 32) | ~idx  -> u64 max == (max dist, then min idx),
//    exactly jnp's argmax tie-break (dist >= 0 so bits are monotone).
//    One st.async per source CTA (8 mbarrier completions per exchange).
//    Full batch xyz lives in SMEM so winner-coordinate fetch is an LDS.
//    Exact jnp semantics preserved:
//      - no FMA contraction: (dx*dx + dy*dy) + dz*dz with __f*_rn
//      - emits the farthest index of the PREVIOUS step (selected[0] = 0)
//    Exchange e (e>=1) delivers winner e on mbar[e&1], parity (e>>1)&1
//    (dummy completed phase 0 on mbar[0] makes the parity formula uniform).
// ============================================================================
__global__ __launch_bounds__(FT, 1) __cluster_dims__(FC, 1, 1)
void fps_cluster_kernel(float* __restrict__ new_xyz) {
    extern __shared__ float smem[];
    float* shx = smem;
    float* shy = smem + NPT;
    float* shz = smem + 2 * NPT;

    int b = blockIdx.x / FC;
    int rank = blockIdx.x % FC;
    int t = threadIdx.x;
    int w = t >> 5, lane = t & 31;
    int base = rank * (NPT / FC);
    const float* sx = g_sx + (size_t)b * NPT;
    const float* sy = g_sy + (size_t)b * NPT;
    const float* sz = g_sz + (size_t)b * NPT;

    // stage full batch coords into SMEM (winner lookup = LDS broadcast)
    for (int i = t; i < NPT; i += FT) {
        shx[i] = sx[i]; shy[i] = sy[i]; shz[i] = sz[i];
    }

    // own slice in registers
    float px[FP], py[FP], pz[FP], dist[FP];
#pragma unroll
    for (int j = 0; j < FP; j++) {
        int i = base + j * FT + t;
        px[j] = sx[i]; py[j] = sy[i]; pz[j] = sz[i];
        dist[j] = 1e10f;
    }

    __shared__ __align__(8) uint64_t c_slot[2][FC];   // [stage][source rank]
    __shared__ __align__(8) uint64_t mbar[2];
    __shared__ __align__(8) uint64_t s_key[8];        // per-warp winners

    uint32_t mb0 = smem_u32(&mbar[0]);
    uint32_t mb1 = smem_u32(&mbar[1]);

    if (t == 0) {
        mbar_inval(mb0); mbar_inval(mb1);
        mbar_init(mb0, 1); mbar_init(mb1, 1);
        mbar_arrive_expect(mb0, 0);    // dummy: complete phase 0 immediately
        mbar_arrive_expect(mb0, XT);   // arm exchange 2 (phase 1)
        mbar_arrive_expect(mb1, XT);   // arm exchange 1 (phase 0)
    }
    __syncthreads();
    // peers' mbarrier init must be visible before any st.async targets them
    asm volatile("barrier.cluster.arrive.aligned;" ::: "memory");
    asm volatile("barrier.cluster.wait.aligned;" ::: "memory");

    // remote addresses: my slot in peer CTA 'lane', both stages + mbars
    uint32_t r_s0 = 0, r_s1 = 0, r_m0 = 0, r_m1 = 0;
    if (w == 0 && lane < FC) {
        r_s0 = mapa_u32(smem_u32(&c_slot[0][rank]), lane);
        r_s1 = mapa_u32(smem_u32(&c_slot[1][rank]), lane);
        r_m0 = mapa_u32(mb0, lane);
        r_m1 = mapa_u32(mb1, lane);
    }

    float curx = shx[0], cury = shy[0], curz = shz[0];   // centroid 0 = point 0
    float* out = new_xyz + (size_t)b * SPT * 3;

    for (int s = 0; s < SPT; s++) {
        if (s > 0) {
            // ---- wait exchange s, pick global winner from 8 u64 keys ----
            uint32_t mb = (s & 1) ? mb1 : mb0;
            mbar_wait(mb, (unsigned)((s >> 1) & 1));
            int bf = s & 1;
            uint64_t wk = c_slot[bf][0];
#pragma unroll
            for (int r = 1; r < FC; r++) {
                uint64_t k = c_slot[bf][r];
                wk = (k > wk) ? k : wk;
            }
            int wi = (int)(~(uint32_t)wk);
            curx = shx[wi]; cury = shy[wi]; curz = shz[wi];
            // re-arm this mbar for exchange s+2 (safe: peers' s+2 stores are
            // gated by our s+1 push, which happens after the sync below)
            if (t == 0 && s + 2 < SPT) mbar_arrive_expect(mb, XT);
        }
        if (rank == 0 && t == 0) {
            out[s * 3 + 0] = curx;
            out[s * 3 + 1] = cury;
            out[s * 3 + 2] = curz;
        }
        // ---- update dists + per-thread argmax (strict > keeps smaller idx) --
        float best = -1.0f; int bj = 0;
#pragma unroll
        for (int j = 0; j < FP; j++) {
            float dx = px[j] - curx, dy = py[j] - cury, dz = pz[j] - curz;
            float d = __fadd_rn(__fadd_rn(__fmul_rn(dx, dx), __fmul_rn(dy, dy)),
                                __fmul_rn(dz, dz));
            float nd = fminf(dist[j], d);
            dist[j] = nd;
            bool bt = nd > best;
            best = bt ? nd : best;
            bj = bt ? j : bj;
        }
        unsigned bi = (unsigned)(base + bj * FT + t);
        unsigned vb = __float_as_uint(best);     // dist >= 0 -> monotone bits
        // ---- warp argmax via REDUX: max value bits, then min index ----
        unsigned mv = __reduce_max_sync(0xffffffffu, vb);
        unsigned cnd = (vb == mv) ? ~bi : 0u;    // ~idx: bigger = smaller idx
        unsigned ml = __reduce_max_sync(0xffffffffu, cnd);
        if (lane == 0) s_key[w] = ((uint64_t)mv << 32) | ml;   // uniform value
        __syncthreads();
        // ---- warp0: block argmax over 8 warps + push key to 8 peers ----
        if (w == 0 && s + 1 < SPT) {
            unsigned hi = (lane < 8) ? (unsigned)(s_key[lane] >> 32) : 0u;
            unsigned lo = (lane < 8) ? (unsigned)s_key[lane] : 0u;
            unsigned mv2 = __reduce_max_sync(0xffffffffu, hi);
            unsigned c2 = (hi == mv2) ? lo : 0u;
            unsigned ml2 = __reduce_max_sync(0xffffffffu, c2);
            if (lane < FC) {
                int st = (s + 1) & 1;
                uint32_t rs = st ? r_s1 : r_s0;
                uint32_t rm = st ? r_m1 : r_m0;
                st_async_u64(rs, rm, ((uint64_t)mv2 << 32) | ml2);
            }
        }
    }
    // keep SMEM alive until every CTA's last consumption is done
    asm volatile("barrier.cluster.arrive.aligned;" ::: "memory");
    asm volatile("barrier.cluster.wait.aligned;" ::: "memory");
}

// ============================================================================
// 2) kNN (k=16). One warp per query; SoA coalesced loads; register top-16
//    per lane over 512 points, then 512 -> 16 selection via shared memory.
//    Only the SET of neighbors matters downstream.
// ============================================================================
__global__ __launch_bounds__(256)
void knn_kernel(const float* __restrict__ new_xyz, int* __restrict__ knn) {
    __shared__ float sd[8][512];
    __shared__ int   si[8][512];
    int w = threadIdx.x >> 5, lane = threadIdx.x & 31;
    int g = blockIdx.x * 8 + w;     // query id 0..8191
    int b = g >> 11;
    const float* sx = g_sx + (size_t)b * NPT;
    const float* sy = g_sy + (size_t)b * NPT;
    const float* sz = g_sz + (size_t)b * NPT;
    float qx = new_xyz[(size_t)g * 3 + 0];
    float qy = new_xyz[(size_t)g * 3 + 1];
    float qz = new_xyz[(size_t)g * 3 + 2];

    float d16[16]; int i16[16];
#pragma unroll
    for (int t = 0; t < 16; t++) { d16[t] = FLT_MAX; i16[t] = 0; }
    float worst = FLT_MAX; int wpos = 0;

    for (int i = 0; i < NPT / 32; i++) {
        int idx = lane + (i << 5);
        float dx = sx[idx] - qx;
        float dy = sy[idx] - qy;
        float dz = sz[idx] - qz;
        float d = dx * dx + dy * dy + dz * dz;
        if (d < worst) {
#pragma unroll
            for (int t = 0; t < 16; t++)
                if (t == wpos) { d16[t] = d; i16[t] = idx; }
            worst = d16[0]; wpos = 0;
#pragma unroll
            for (int t = 1; t < 16; t++)
                if (d16[t] > worst) { worst = d16[t]; wpos = t; }
        }
    }
#pragma unroll
    for (int t = 0; t < 16; t++) {
        sd[w][lane * 16 + t] = d16[t];
        si[w][lane * 16 + t] = i16[t];
    }
    __syncwarp();
    for (int r = 0; r < 16; r++) {
        float mv = FLT_MAX; int mp = 0;
#pragma unroll
        for (int t = 0; t < 16; t++) {
            float v = sd[w][lane * 16 + t];
            if (v < mv) { mv = v; mp = lane * 16 + t; }
        }
#pragma unroll
        for (int off = 16; off; off >>= 1) {
            float ov = __shfl_down_sync(0xffffffffu, mv, off);
            int   op = __shfl_down_sync(0xffffffffu, mp, off);
            if (ov < mv) { mv = ov; mp = op; }
        }
        mp = __shfl_sync(0xffffffffu, mp, 0);
        if (lane == 0) {
            knn[(size_t)g * 16 + r] = si[w][mp];
            sd[w][mp] = FLT_MAX;
        }
        __syncwarp();
    }
}

// ============================================================================
// 3) Build MLP input: x1[n][0:3] = xyz[nbr]-query, x1[n][3:128] = feat[nbr].
// ============================================================================
__global__ __launch_bounds__(256)
void build_kernel(const float* __restrict__ feat,
                  const int* __restrict__ knn, const float* __restrict__ new_xyz,
                  float* __restrict__ x1) {
    int w = threadIdx.x >> 5, lane = threadIdx.x & 31;
    int n = blockIdx.x * 8 + w;   // 0..131071
    int g = n >> 4;               // query id
    int b = g >> 11;
    int idx = knn[n];
    const float* f = feat + ((size_t)b * NPT + idx) * DFEAT;
    float* dst = x1 + (size_t)n * C0;
#pragma unroll
    for (int t = 0; t < 4; t++) {
        int c = lane + t * 32;
        float v;
        if (c == 0)      v = g_sx[(size_t)b * NPT + idx] - new_xyz[(size_t)g * 3 + 0];
        else if (c == 1) v = g_sy[(size_t)b * NPT + idx] - new_xyz[(size_t)g * 3 + 1];
        else if (c == 2) v = g_sz[(size_t)b * NPT + idx] - new_xyz[(size_t)g * 3 + 2];
        else             v = f[c - 3];
        dst[c] = v;
    }
}

// ============================================================================
// 4) GEMM: Y[m][c] = sum_k A'[m][k] * W[c][k] + bias, K = 128 fixed.
//    Fusions:
//      fuseA:    A' = relu(A*aScale[k] + aBias[k])   (BN1+ReLU on input)
//      fuseMax:  raw max over each group of 16 rows -> gmax
//      fuseStats: per-mblock column sum/sumsq partials -> part (BN stats)
//    Y store skipped when Y == nullptr.
// ============================================================================
__global__ __launch_bounds__(256, 2)
void gemm_kernel(const float* __restrict__ A, const float* __restrict__ W,
                 const float* __restrict__ bias, float* __restrict__ Y, int Nout,
                 const float* __restrict__ aScale, const float* __restrict__ aBias,
                 int fuseA, float* __restrict__ gmax, int fuseMax,
                 float* __restrict__ part, int fuseStats) {
    const int K = 128;
    __shared__ float As[16][64];
    __shared__ float Ws[16][128];
    __shared__ float red0[16][128];
    __shared__ float red1[16][128];
    int m0 = blockIdx.x * 64;
    int c0 = blockIdx.y * 128;
    int tid = threadIdx.x;
    int tx = tid & 15, ty = tid >> 4;

    float acc[4][8];
#pragma unroll
    for (int i = 0; i < 4; i++)
#pragma unroll
        for (int j = 0; j < 8; j++) acc[i][j] = 0.0f;

    for (int k0 = 0; k0 < K; k0 += 16) {
        {
            int m = tid >> 2, kv = (tid & 3) * 4;
            float4 a = *(const float4*)&A[(size_t)(m0 + m) * K + k0 + kv];
            if (fuseA) {
                float4 sc = *(const float4*)&aScale[k0 + kv];
                float4 bi = *(const float4*)&aBias[k0 + kv];
                a.x = fmaxf(fmaf(a.x, sc.x, bi.x), 0.0f);
                a.y = fmaxf(fmaf(a.y, sc.y, bi.y), 0.0f);
                a.z = fmaxf(fmaf(a.z, sc.z, bi.z), 0.0f);
                a.w = fmaxf(fmaf(a.w, sc.w, bi.w), 0.0f);
            }
            As[kv + 0][m] = a.x; As[kv + 1][m] = a.y;
            As[kv + 2][m] = a.z; As[kv + 3][m] = a.w;
        }
        {
            int kv = (tid & 3) * 4;
#pragma unroll
            for (int r = 0; r < 2; r++) {
                int c = (tid >> 2) + 64 * r;
                float4 wv = *(const float4*)&W[(size_t)(c0 + c) * K + k0 + kv];
                Ws[kv + 0][c] = wv.x; Ws[kv + 1][c] = wv.y;
                Ws[kv + 2][c] = wv.z; Ws[kv + 3][c] = wv.w;
            }
        }
        __syncthreads();
#pragma unroll
        for (int kk = 0; kk < 16; kk++) {
            float4 a  = *(const float4*)&As[kk][ty * 4];
            float4 b0 = *(const float4*)&Ws[kk][tx * 8];
            float4 b1 = *(const float4*)&Ws[kk][tx * 8 + 4];
            float av[4] = {a.x, a.y, a.z, a.w};
            float bv[8] = {b0.x, b0.y, b0.z, b0.w, b1.x, b1.y, b1.z, b1.w};
#pragma unroll
            for (int i = 0; i < 4; i++)
#pragma unroll
                for (int j = 0; j < 8; j++) acc[i][j] += av[i] * bv[j];
        }
        __syncthreads();
    }
#pragma unroll
    for (int i = 0; i < 4; i++)
#pragma unroll
        for (int j = 0; j < 8; j++) acc[i][j] += bias[c0 + tx * 8 + j];

    if (Y) {
#pragma unroll
        for (int i = 0; i < 4; i++) {
            size_t row = (size_t)(m0 + ty * 4 + i) * Nout + c0 + tx * 8;
#pragma unroll
            for (int j = 0; j < 8; j++) Y[row + j] = acc[i][j];
        }
    }
    if (fuseMax) {
        // each thread's 4 rows lie in one group of 16 (group id = ty/4)
#pragma unroll
        for (int j = 0; j < 8; j++) {
            float m = fmaxf(fmaxf(acc[0][j], acc[1][j]), fmaxf(acc[2][j], acc[3][j]));
            red0[ty][tx * 8 + j] = m;
        }
        __syncthreads();
        if (ty < 4) {   // ty = group 0..3 within this 64-row tile
#pragma unroll
            for (int j = 0; j < 8; j++) {
                int c = tx * 8 + j;
                float m = fmaxf(fmaxf(red0[ty * 4 + 0][c], red0[ty * 4 + 1][c]),
                                fmaxf(red0[ty * 4 + 2][c], red0[ty * 4 + 3][c]));
                gmax[(size_t)(m0 / 16 + ty) * Nout + c0 + c] = m;
            }
        }
        __syncthreads();
    }
    if (fuseStats) {
#pragma unroll
        for (int j = 0; j < 8; j++) {
            float s = acc[0][j] + acc[1][j] + acc[2][j] + acc[3][j];
            float q = acc[0][j] * acc[0][j] + acc[1][j] * acc[1][j]
                    + acc[2][j] * acc[2][j] + acc[3][j] * acc[3][j];
            red0[ty][tx * 8 + j] = s;
            red1[ty][tx * 8 + j] = q;
        }
        __syncthreads();
        if (tid < 128) {          // thread = column within this 128-col tile
            float S = 0.0f, Q = 0.0f;
#pragma unroll
            for (int i = 0; i < 16; i++) { S += red0[i][tid]; Q += red1[i][tid]; }
            size_t o = (size_t)(m0 / 64) * Nout + c0 + tid;
            part[o] = S;
            part[PSQ_OFF + o] = Q;
        }
    }
}

// ============================================================================
// 5) BN stats reduction: stage 1 folds 2048 m-block partials into 32,
//    stage 2 (finalize) folds 32 and emits scale/bias.
// ============================================================================
__global__ void reduce_kernel(const float* __restrict__ part, float* __restrict__ red, int C) {
    int c = threadIdx.x;          // blockDim = C
    int r = blockIdx.x;           // 0..31
    float S = 0.0f, Q = 0.0f;
    for (int m = r * 64; m < r * 64 + 64; m++) {
        size_t o = (size_t)m * C + c;
        S += part[o];
        Q += part[PSQ_OFF + o];
    }
    red[r * C + c] = S;
    red[RSQ_OFF + r * C + c] = Q;
}

__global__ void finalize_kernel(const float* __restrict__ red,
                                const float* __restrict__ gamma,
                                const float* __restrict__ beta,
                                float* __restrict__ scale, float* __restrict__ bias, int C) {
    int c = threadIdx.x;
    float s = 0.0f, q = 0.0f;
    for (int r = 0; r < 32; r++) {
        s += red[r * C + c];
        q += red[RSQ_OFF + r * C + c];
    }
    const float inv = 1.0f / (float)MROWS;
    float m = s * inv;
    float v = q * inv - m * m;
    float sc = gamma[c] * rsqrtf(v + 1e-5f);
    scale[c] = sc;
    bias[c] = beta[c] - m * sc;
}

// ============================================================================
// 6) BN2 + ReLU on the pre-reduced group max (monotone: scale > 0).
// ============================================================================
__global__ __launch_bounds__(256, 4)
void maxpool_kernel(const float* __restrict__ gmax, const float* __restrict__ scale,
                    const float* __restrict__ bias, float* __restrict__ out) {
    int g = blockIdx.x;      // (b,s) 0..8191
    int c = threadIdx.x;     // channel 0..255
    float v = fmaf(gmax[(size_t)g * C2 + c], scale[c], bias[c]);
    out[(size_t)g * C2 + c] = fmaxf(v, 0.0f);
}

// ============================================================================
extern "C" void kernel_launch(void* const* d_in, const int* in_sizes, int n_in,
                              void* d_out, int out_size) {
    const float* xyz    = (const float*)d_in[0];
    const float* feat   = (const float*)d_in[1];
    const float* W1     = (const float*)d_in[2];
    const float* b1     = (const float*)d_in[3];
    const float* gamma1 = (const float*)d_in[4];
    const float* beta1  = (const float*)d_in[5];
    const float* W2     = (const float*)d_in[6];
    const float* b2     = (const float*)d_in[7];
    const float* gamma2 = (const float*)d_in[8];
    const float* beta2  = (const float*)d_in[9];

    float* out = (float*)d_out;
    float* out_newxyz = out;                            // [B,S,3]
    float* out_x      = out + (size_t)BATCH * SPT * 3;  // [B,S,C2]

    float *x1, *y1, *gmax, *part, *red, *scale, *bias;
    int *knni;
    cudaGetSymbolAddress((void**)&x1,    g_x1);
    cudaGetSymbolAddress((void**)&y1,    g_y1);
    cudaGetSymbolAddress((void**)&gmax,  g_max);
    cudaGetSymbolAddress((void**)&part,  g_part);
    cudaGetSymbolAddress((void**)&red,   g_red);
    cudaGetSymbolAddress((void**)&scale, g_scale);
    cudaGetSymbolAddress((void**)&bias,  g_bias);
    cudaGetSymbolAddress((void**)&knni,  g_knn);

    // 0. SoA transpose of xyz
    soa_kernel<<<(BATCH * NPT) / 256, 256>>>(xyz);
    // 1. FPS (cluster kernel; writes new_xyz directly to output)
    cudaFuncSetAttribute(fps_cluster_kernel,
                         cudaFuncAttributeMaxDynamicSharedMemorySize, FPS_SMEM);
    fps_cluster_kernel<<<BATCH * FC, FT, FPS_SMEM>>>(out_newxyz);
    // 2. kNN
    knn_kernel<<<(BATCH * SPT) / 8, 256>>>(out_newxyz, knni);
    // 3. gather + concat
    build_kernel<<<MROWS / 8, 256>>>(feat, knni, out_newxyz, x1);
    // 4. conv1 with fused BN1-stats partials (y1 kept for gemm2 input)
    {
        dim3 grid(MBLK, C1 / 128);
        gemm_kernel<<<grid, 256>>>(x1, W1, b1, y1, C1, nullptr, nullptr, 0,
                                   nullptr, 0, part, 1);
    }
    reduce_kernel<<<32, C1>>>(part, red, C1);
    finalize_kernel<<<1, C1>>>(red, gamma1, beta1, scale, bias, C1);
    // 5. conv2: fused BN1+ReLU input, group-max + BN2-stats epilogue, no Y
    {
        dim3 grid(MBLK, C2 / 128);
        gemm_kernel<<<grid, 256>>>(y1, W2, b2, nullptr, C2, scale, bias, 1,
                                   gmax, 1, part, 1);
    }
    reduce_kernel<<<32, C2>>>(part, red, C2);
    finalize_kernel<<<1, C2>>>(red, gamma2, beta2, scale, bias, C2);
    // 6. BN2+ReLU on pre-reduced max -> output
    maxpool_kernel<<<BATCH * SPT, C2>>>(gmax, scale, bias, out_x);
}

// round 9
// speedup vs baseline: 2.3491x; 1.0256x over previous
#include <cuda_runtime.h>
#include <cuda_bf16.h>
#include <cstdint>
#include <float.h>

// Problem constants (shapes fixed by the dataset)
#define BATCH 4
#define NPT   16384
#define SPT   2048
#define KNN   16
#define DFEAT 125
#define C0    128
#define C1    128
#define C2    256
#define MROWS (BATCH * SPT * KNN)   // 131072 samples through the MLP
#define MBLK  (MROWS / 128)         // 1024 gemm m-blocks (128-row tiles)
#define PSQ_OFF (MBLK * 256)        // sumsq offset inside g_part
#define RSQ_OFF (32 * 256)          // sumsq offset inside g_red

// FPS cluster config: 8 CTAs x 256 threads per batch
#define FC 8
#define FT 256
#define FP (NPT / FC / FT)          // 8 points per thread
#define FPS_SMEM (3 * NPT * 4)      // full batch xyz in SMEM (192 KB)

// ---------------- scratch (static device globals; no allocation allowed) ----
__device__ float g_x1[(size_t)MROWS * C0];     // gathered/concat input
__device__ float g_y1[(size_t)MROWS * C1];     // conv1 out (raw, pre-BN)
__device__ float g_max[(size_t)BATCH * SPT * C2]; // raw per-group max (8.4MB)
__device__ float g_part[2 * MBLK * 256];       // per-mblock [sum | sumsq]
__device__ float g_red[2 * 32 * 256];          // stage-1 reduced partials
__device__ float g_scale[256];
__device__ float g_bias[256];
__device__ int   g_knn[BATCH * SPT * KNN];
__device__ float g_sx[BATCH * NPT];            // SoA xyz
__device__ float g_sy[BATCH * NPT];
__device__ float g_sz[BATCH * NPT];

// ---------------------------------------------------------------------------
// helpers: DSMEM
// ---------------------------------------------------------------------------
__device__ __forceinline__ uint32_t smem_u32(const void* p) {
    return (uint32_t)__cvta_generic_to_shared(p);
}
__device__ __forceinline__ uint32_t mapa_u32(uint32_t addr, uint32_t rank) {
    uint32_t r;
    asm("mapa.shared::cluster.u32 %0, %1, %2;" : "=r"(r) : "r"(addr), "r"(rank));
    return r;
}
// relaxed 8B store into peer CTA's SMEM (value itself is the signal)
__device__ __forceinline__ void st_rel_u64(uint32_t raddr, uint64_t v) {
    asm volatile("st.relaxed.cluster.shared::cluster.b64 [%0], %1;"
                 :: "r"(raddr), "l"(v) : "memory");
}
__device__ __forceinline__ uint64_t ld_vol_u64(const void* p) {
    uint64_t v;
    asm volatile("ld.volatile.shared.b64 %0, [%1];" : "=l"(v) : "r"(smem_u32(p)) : "memory");
    return v;
}

// ============================================================================
// 0) AoS -> SoA transpose of xyz (coalesced via smem staging)
// ============================================================================
__global__ __launch_bounds__(256)
void soa_kernel(const float* __restrict__ xyz) {
    __shared__ float buf[768];
    int t = threadIdx.x;
    size_t base = (size_t)blockIdx.x * 768;
#pragma unroll
    for (int r = 0; r < 3; r++) buf[t + 256 * r] = xyz[base + t + 256 * r];
    __syncthreads();
    size_t o = (size_t)blockIdx.x * 256 + t;
    g_sx[o] = buf[t * 3 + 0];
    g_sy[o] = buf[t * 3 + 1];
    g_sz[o] = buf[t * 3 + 2];
}

// ============================================================================
// 1) FPS: 8-CTA x 256-thread cluster per batch. Single u64 candidate key
//    key = (dist_bits << 32) | ~idx  -> u64 max == (max dist, then min idx),
//    exactly jnp's argmax tie-break (dist >= 0 so bits are monotone).
//    NO mbarrier: peers st.relaxed the key into my slot; key is never 0
//    (low word = ~idx, idx < 16384), so polling the 8 slots for nonzero is
//    the completion signal. Double-buffered stages; consumed stage is zeroed
//    after the block sync, provably before any peer's stage-reuse write
//    (peer's s+2 push is gated on receiving my s+1 push, >= 1 DSMEM RTT).
//    Exact jnp semantics preserved:
//      - no FMA contraction: (dx*dx + dy*dy) + dz*dz with __f*_rn
//      - emits the farthest index of the PREVIOUS step (selected[0] = 0)
// ============================================================================
__global__ __launch_bounds__(FT, 1) __cluster_dims__(FC, 1, 1)
void fps_cluster_kernel(float* __restrict__ new_xyz) {
    extern __shared__ float smem[];
    float* shx = smem;
    float* shy = smem + NPT;
    float* shz = smem + 2 * NPT;

    int b = blockIdx.x / FC;
    int rank = blockIdx.x % FC;
    int t = threadIdx.x;
    int w = t >> 5, lane = t & 31;
    int base = rank * (NPT / FC);
    const float* sx = g_sx + (size_t)b * NPT;
    const float* sy = g_sy + (size_t)b * NPT;
    const float* sz = g_sz + (size_t)b * NPT;

    // stage full batch coords into SMEM (winner lookup = LDS broadcast)
    for (int i = t; i < NPT; i += FT) {
        shx[i] = sx[i]; shy[i] = sy[i]; shz[i] = sz[i];
    }

    // own slice in registers
    float px[FP], py[FP], pz[FP], dist[FP];
#pragma unroll
    for (int j = 0; j < FP; j++) {
        int i = base + j * FT + t;
        px[j] = sx[i]; py[j] = sy[i]; pz[j] = sz[i];
        dist[j] = 1e10f;
    }

    __shared__ __align__(8) uint64_t c_slot[2][FC];   // [stage][source rank]
    __shared__ __align__(8) uint64_t s_key[8];        // per-warp winners

    if (t < 2 * FC) ((uint64_t*)c_slot)[t] = 0;       // sentinel = 0
    __syncthreads();
    // slots must be zeroed cluster-wide before any peer pushes
    asm volatile("barrier.cluster.arrive.aligned;" ::: "memory");
    asm volatile("barrier.cluster.wait.aligned;" ::: "memory");

    // remote addresses of MY slot in peer CTA 'lane', both stages
    uint32_t r_s0 = 0, r_s1 = 0;
    if (w == 0 && lane < FC) {
        r_s0 = mapa_u32(smem_u32(&c_slot[0][rank]), lane);
        r_s1 = mapa_u32(smem_u32(&c_slot[1][rank]), lane);
    }

    float curx = shx[0], cury = shy[0], curz = shz[0];   // centroid 0 = point 0
    float* out = new_xyz + (size_t)b * SPT * 3;

    for (int s = 0; s < SPT; s++) {
        if (s > 0) {
            // ---- poll stage bf until all 8 keys arrived, pick winner ----
            int bf = s & 1;
            uint64_t k[FC];
            for (;;) {
                bool ok = true;
#pragma unroll
                for (int r = 0; r < FC; r++) {
                    k[r] = ld_vol_u64(&c_slot[bf][r]);
                    ok &= (k[r] != 0);
                }
                if (ok) break;
                __nanosleep(16);
            }
            uint64_t wk = k[0];
#pragma unroll
            for (int r = 1; r < FC; r++) wk = (k[r] > wk) ? k[r] : wk;
            int wi = (int)(~(uint32_t)wk);
            curx = shx[wi]; cury = shy[wi]; curz = shz[wi];
        }
        if (rank == 0 && t == 0) {
            out[s * 3 + 0] = curx;
            out[s * 3 + 1] = cury;
            out[s * 3 + 2] = curz;
        }
        // ---- update dists + per-thread argmax (strict > keeps smaller idx) --
        float best = -1.0f; int bj = 0;
#pragma unroll
        for (int j = 0; j < FP; j++) {
            float dx = px[j] - curx, dy = py[j] - cury, dz = pz[j] - curz;
            float d = __fadd_rn(__fadd_rn(__fmul_rn(dx, dx), __fmul_rn(dy, dy)),
                                __fmul_rn(dz, dz));
            float nd = fminf(dist[j], d);
            dist[j] = nd;
            bool bt = nd > best;
            best = bt ? nd : best;
            bj = bt ? j : bj;
        }
        unsigned bi = (unsigned)(base + bj * FT + t);
        unsigned vb = __float_as_uint(best);     // dist >= 0 -> monotone bits
        // ---- warp argmax via REDUX: max value bits, then min index ----
        unsigned mv = __reduce_max_sync(0xffffffffu, vb);
        unsigned cnd = (vb == mv) ? ~bi : 0u;    // ~idx: bigger = smaller idx
        unsigned ml = __reduce_max_sync(0xffffffffu, cnd);
        if (lane == 0) s_key[w] = ((uint64_t)mv << 32) | ml;   // uniform value
        __syncthreads();
        // ---- warp0: block argmax over 8 warps; push key; zero used stage ---
        if (w == 0) {
            if (s + 1 < SPT) {
                unsigned hi = (lane < 8) ? (unsigned)(s_key[lane] >> 32) : 0u;
                unsigned lo = (lane < 8) ? (unsigned)s_key[lane] : 0u;
                unsigned mv2 = __reduce_max_sync(0xffffffffu, hi);
                unsigned c2 = (hi == mv2) ? lo : 0u;
                unsigned ml2 = __reduce_max_sync(0xffffffffu, c2);
                if (lane < FC) {
                    uint32_t rs = ((s + 1) & 1) ? r_s1 : r_s0;
                    st_rel_u64(rs, ((uint64_t)mv2 << 32) | ml2);
                }
            }
            if (s > 0 && lane >= 16 && lane < 16 + FC)
                c_slot[s & 1][lane - 16] = 0;     // reset consumed stage
        }
    }
    // keep SMEM alive until every CTA's last consumption is done
    asm volatile("barrier.cluster.arrive.aligned;" ::: "memory");
    asm volatile("barrier.cluster.wait.aligned;" ::: "memory");
}

// ============================================================================
// 2) kNN (k=16). One warp per query; SoA coalesced loads; register top-16
//    per lane over 512 points, then 512 -> 16 selection via shared memory.
//    Only the SET of neighbors matters downstream.
// ============================================================================
__global__ __launch_bounds__(256)
void knn_kernel(const float* __restrict__ new_xyz, int* __restrict__ knn) {
    __shared__ float sd[8][512];
    __shared__ int   si[8][512];
    int w = threadIdx.x >> 5, lane = threadIdx.x & 31;
    int g = blockIdx.x * 8 + w;     // query id 0..8191
    int b = g >> 11;
    const float* sx = g_sx + (size_t)b * NPT;
    const float* sy = g_sy + (size_t)b * NPT;
    const float* sz = g_sz + (size_t)b * NPT;
    float qx = new_xyz[(size_t)g * 3 + 0];
    float qy = new_xyz[(size_t)g * 3 + 1];
    float qz = new_xyz[(size_t)g * 3 + 2];

    float d16[16]; int i16[16];
#pragma unroll
    for (int t = 0; t < 16; t++) { d16[t] = FLT_MAX; i16[t] = 0; }
    float worst = FLT_MAX; int wpos = 0;

    for (int i = 0; i < NPT / 32; i++) {
        int idx = lane + (i << 5);
        float dx = sx[idx] - qx;
        float dy = sy[idx] - qy;
        float dz = sz[idx] - qz;
        float d = dx * dx + dy * dy + dz * dz;
        if (d < worst) {
#pragma unroll
            for (int t = 0; t < 16; t++)
                if (t == wpos) { d16[t] = d; i16[t] = idx; }
            worst = d16[0]; wpos = 0;
#pragma unroll
            for (int t = 1; t < 16; t++)
                if (d16[t] > worst) { worst = d16[t]; wpos = t; }
        }
    }
#pragma unroll
    for (int t = 0; t < 16; t++) {
        sd[w][lane * 16 + t] = d16[t];
        si[w][lane * 16 + t] = i16[t];
    }
    __syncwarp();
    for (int r = 0; r < 16; r++) {
        float mv = FLT_MAX; int mp = 0;
#pragma unroll
        for (int t = 0; t < 16; t++) {
            float v = sd[w][lane * 16 + t];
            if (v < mv) { mv = v; mp = lane * 16 + t; }
        }
#pragma unroll
        for (int off = 16; off; off >>= 1) {
            float ov = __shfl_down_sync(0xffffffffu, mv, off);
            int   op = __shfl_down_sync(0xffffffffu, mp, off);
            if (ov < mv) { mv = ov; mp = op; }
        }
        mp = __shfl_sync(0xffffffffu, mp, 0);
        if (lane == 0) {
            knn[(size_t)g * 16 + r] = si[w][mp];
            sd[w][mp] = FLT_MAX;
        }
        __syncwarp();
    }
}

// ============================================================================
// 3) Build MLP input: x1[n][0:3] = xyz[nbr]-query, x1[n][3:128] = feat[nbr].
// ============================================================================
__global__ __launch_bounds__(256)
void build_kernel(const float* __restrict__ feat,
                  const int* __restrict__ knn, const float* __restrict__ new_xyz,
                  float* __restrict__ x1) {
    int w = threadIdx.x >> 5, lane = threadIdx.x & 31;
    int n = blockIdx.x * 8 + w;   // 0..131071
    int g = n >> 4;               // query id
    int b = g >> 11;
    int idx = knn[n];
    const float* f = feat + ((size_t)b * NPT + idx) * DFEAT;
    float* dst = x1 + (size_t)n * C0;
#pragma unroll
    for (int t = 0; t < 4; t++) {
        int c = lane + t * 32;
        float v;
        if (c == 0)      v = g_sx[(size_t)b * NPT + idx] - new_xyz[(size_t)g * 3 + 0];
        else if (c == 1) v = g_sy[(size_t)b * NPT + idx] - new_xyz[(size_t)g * 3 + 1];
        else if (c == 2) v = g_sz[(size_t)b * NPT + idx] - new_xyz[(size_t)g * 3 + 2];
        else             v = f[c - 3];
        dst[c] = v;
    }
}

// ============================================================================
// 4) GEMM: Y[m][c] = sum_k A'[m][k] * W[c][k] + bias, K = 128 fixed.
//    128(M) x 128(N) block tile, 256 threads, 8x8 register tile / thread.
//    Fusions:
//      fuseA:    A' = relu(A*aScale[k] + aBias[k])   (BN1+ReLU on input)
//      fuseMax:  raw max over each group of 16 rows -> gmax
//      fuseStats: per-mblock column sum/sumsq partials -> part (BN stats)
//    Y store skipped when Y == nullptr. As/Ws reused for epilogue reductions.
// ============================================================================
__global__ __launch_bounds__(256, 2)
void gemm_kernel(const float* __restrict__ A, const float* __restrict__ W,
                 const float* __restrict__ bias, float* __restrict__ Y, int Nout,
                 const float* __restrict__ aScale, const float* __restrict__ aBias,
                 int fuseA, float* __restrict__ gmax, int fuseMax,
                 float* __restrict__ part, int fuseStats) {
    const int K = 128;
    __shared__ float As[16][128];
    __shared__ float Ws[16][128];
    int m0 = blockIdx.x * 128;
    int c0 = blockIdx.y * 128;
    int tid = threadIdx.x;
    int tx = tid & 15, ty = tid >> 4;
    int lrow = tid & 127, khalf = tid >> 7;

    float acc[8][8];
#pragma unroll
    for (int i = 0; i < 8; i++)
#pragma unroll
        for (int j = 0; j < 8; j++) acc[i][j] = 0.0f;

    for (int k0 = 0; k0 < K; k0 += 16) {
        {
            const float* ap = &A[(size_t)(m0 + lrow) * K + k0 + khalf * 8];
            float4 a0 = *(const float4*)ap;
            float4 a1 = *(const float4*)(ap + 4);
            if (fuseA) {
                const float* sp = &aScale[k0 + khalf * 8];
                const float* bp = &aBias[k0 + khalf * 8];
                float4 s0 = *(const float4*)sp, s1 = *(const float4*)(sp + 4);
                float4 q0 = *(const float4*)bp, q1 = *(const float4*)(bp + 4);
                a0.x = fmaxf(fmaf(a0.x, s0.x, q0.x), 0.0f);
                a0.y = fmaxf(fmaf(a0.y, s0.y, q0.y), 0.0f);
                a0.z = fmaxf(fmaf(a0.z, s0.z, q0.z), 0.0f);
                a0.w = fmaxf(fmaf(a0.w, s0.w, q0.w), 0.0f);
                a1.x = fmaxf(fmaf(a1.x, s1.x, q1.x), 0.0f);
                a1.y = fmaxf(fmaf(a1.y, s1.y, q1.y), 0.0f);
                a1.z = fmaxf(fmaf(a1.z, s1.z, q1.z), 0.0f);
                a1.w = fmaxf(fmaf(a1.w, s1.w, q1.w), 0.0f);
            }
            int kb = khalf * 8;
            As[kb + 0][lrow] = a0.x; As[kb + 1][lrow] = a0.y;
            As[kb + 2][lrow] = a0.z; As[kb + 3][lrow] = a0.w;
            As[kb + 4][lrow] = a1.x; As[kb + 5][lrow] = a1.y;
            As[kb + 6][lrow] = a1.z; As[kb + 7][lrow] = a1.w;

            const float* wp = &W[(size_t)(c0 + lrow) * K + k0 + khalf * 8];
            float4 w0 = *(const float4*)wp;
            float4 w1 = *(const float4*)(wp + 4);
            Ws[kb + 0][lrow] = w0.x; Ws[kb + 1][lrow] = w0.y;
            Ws[kb + 2][lrow] = w0.z; Ws[kb + 3][lrow] = w0.w;
            Ws[kb + 4][lrow] = w1.x; Ws[kb + 5][lrow] = w1.y;
            Ws[kb + 6][lrow] = w1.z; Ws[kb + 7][lrow] = w1.w;
        }
        __syncthreads();
#pragma unroll
        for (int kk = 0; kk < 16; kk++) {
            float4 xa0 = *(const float4*)&As[kk][ty * 8];
            float4 xa1 = *(const float4*)&As[kk][ty * 8 + 4];
            float4 xb0 = *(const float4*)&Ws[kk][tx * 8];
            float4 xb1 = *(const float4*)&Ws[kk][tx * 8 + 4];
            float av[8] = {xa0.x, xa0.y, xa0.z, xa0.w, xa1.x, xa1.y, xa1.z, xa1.w};
            float bv[8] = {xb0.x, xb0.y, xb0.z, xb0.w, xb1.x, xb1.y, xb1.z, xb1.w};
#pragma unroll
            for (int i = 0; i < 8; i++)
#pragma unroll
                for (int j = 0; j < 8; j++) acc[i][j] += av[i] * bv[j];
        }
        __syncthreads();
    }
#pragma unroll
    for (int i = 0; i < 8; i++)
#pragma unroll
        for (int j = 0; j < 8; j++) acc[i][j] += bias[c0 + tx * 8 + j];

    if (Y) {
#pragma unroll
        for (int i = 0; i < 8; i++) {
            size_t row = (size_t)(m0 + ty * 8 + i) * Nout + c0 + tx * 8;
            float4 v0 = {acc[i][0], acc[i][1], acc[i][2], acc[i][3]};
            float4 v1 = {acc[i][4], acc[i][5], acc[i][6], acc[i][7]};
            *(float4*)&Y[row] = v0;
            *(float4*)&Y[row + 4] = v1;
        }
    }
    if (fuseMax) {
        float (*redm)[128] = As;   // reuse (post-sync)
#pragma unroll
        for (int j = 0; j < 8; j++) {
            float m = acc[0][j];
#pragma unroll
            for (int i = 1; i < 8; i++) m = fmaxf(m, acc[i][j]);
            redm[ty][tx * 8 + j] = m;
        }
        __syncthreads();
        if (ty < 8) {   // 8 groups of 16 rows in this 128-row tile
#pragma unroll
            for (int j = 0; j < 8; j++) {
                int c = tx * 8 + j;
                float m = fmaxf(redm[2 * ty][c], redm[2 * ty + 1][c]);
                gmax[(size_t)(m0 / 16 + ty) * Nout + c0 + c] = m;
            }
        }
        __syncthreads();
    }
    if (fuseStats) {
        float (*r0)[128] = As;
        float (*r1)[128] = Ws;
#pragma unroll
        for (int j = 0; j < 8; j++) {
            float s = 0.0f, q = 0.0f;
#pragma unroll
            for (int i = 0; i < 8; i++) { s += acc[i][j]; q += acc[i][j] * acc[i][j]; }
            r0[ty][tx * 8 + j] = s;
            r1[ty][tx * 8 + j] = q;
        }
        __syncthreads();
        if (tid < 128) {          // thread = column within this 128-col tile
            float S = 0.0f, Q = 0.0f;
#pragma unroll
            for (int i = 0; i < 16; i++) { S += r0[i][tid]; Q += r1[i][tid]; }
            size_t o = (size_t)(m0 / 128) * Nout + c0 + tid;
            part[o] = S;
            part[PSQ_OFF + o] = Q;
        }
    }
}

// ============================================================================
// 5) BN stats reduction: stage 1 folds 1024 m-block partials into 32,
//    stage 2 (finalize) folds 32 and emits scale/bias.
// ============================================================================
__global__ void reduce_kernel(const float* __restrict__ part, float* __restrict__ red, int C) {
    int c = threadIdx.x;          // blockDim = C
    int r = blockIdx.x;           // 0..31
    float S = 0.0f, Q = 0.0f;
    for (int m = r * 32; m < r * 32 + 32; m++) {
        size_t o = (size_t)m * C + c;
        S += part[o];
        Q += part[PSQ_OFF + o];
    }
    red[r * C + c] = S;
    red[RSQ_OFF + r * C + c] = Q;
}

__global__ void finalize_kernel(const float* __restrict__ red,
                                const float* __restrict__ gamma,
                                const float* __restrict__ beta,
                                float* __restrict__ scale, float* __restrict__ bias, int C) {
    int c = threadIdx.x;
    float s = 0.0f, q = 0.0f;
    for (int r = 0; r < 32; r++) {
        s += red[r * C + c];
        q += red[RSQ_OFF + r * C + c];
    }
    const float inv = 1.0f / (float)MROWS;
    float m = s * inv;
    float v = q * inv - m * m;
    float sc = gamma[c] * rsqrtf(v + 1e-5f);
    scale[c] = sc;
    bias[c] = beta[c] - m * sc;
}

// ============================================================================
// 6) BN2 + ReLU on the pre-reduced group max (monotone: scale > 0).
// ============================================================================
__global__ __launch_bounds__(256, 4)
void maxpool_kernel(const float* __restrict__ gmax, const float* __restrict__ scale,
                    const float* __restrict__ bias, float* __restrict__ out) {
    int g = blockIdx.x;      // (b,s) 0..8191
    int c = threadIdx.x;     // channel 0..255
    float v = fmaf(gmax[(size_t)g * C2 + c], scale[c], bias[c]);
    out[(size_t)g * C2 + c] = fmaxf(v, 0.0f);
}

// ============================================================================
extern "C" void kernel_launch(void* const* d_in, const int* in_sizes, int n_in,
                              void* d_out, int out_size) {
    const float* xyz    = (const float*)d_in[0];
    const float* feat   = (const float*)d_in[1];
    const float* W1     = (const float*)d_in[2];
    const float* b1     = (const float*)d_in[3];
    const float* gamma1 = (const float*)d_in[4];
    const float* beta1  = (const float*)d_in[5];
    const float* W2     = (const float*)d_in[6];
    const float* b2     = (const float*)d_in[7];
    const float* gamma2 = (const float*)d_in[8];
    const float* beta2  = (const float*)d_in[9];

    float* out = (float*)d_out;
    float* out_newxyz = out;                            // [B,S,3]
    float* out_x      = out + (size_t)BATCH * SPT * 3;  // [B,S,C2]

    float *x1, *y1, *gmax, *part, *red, *scale, *bias;
    int *knni;
    cudaGetSymbolAddress((void**)&x1,    g_x1);
    cudaGetSymbolAddress((void**)&y1,    g_y1);
    cudaGetSymbolAddress((void**)&gmax,  g_max);
    cudaGetSymbolAddress((void**)&part,  g_part);
    cudaGetSymbolAddress((void**)&red,   g_red);
    cudaGetSymbolAddress((void**)&scale, g_scale);
    cudaGetSymbolAddress((void**)&bias,  g_bias);
    cudaGetSymbolAddress((void**)&knni,  g_knn);

    // 0. SoA transpose of xyz
    soa_kernel<<<(BATCH * NPT) / 256, 256>>>(xyz);
    // 1. FPS (cluster kernel; writes new_xyz directly to output)
    cudaFuncSetAttribute(fps_cluster_kernel,
                         cudaFuncAttributeMaxDynamicSharedMemorySize, FPS_SMEM);
    fps_cluster_kernel<<<BATCH * FC, FT, FPS_SMEM>>>(out_newxyz);
    // 2. kNN
    knn_kernel<<<(BATCH * SPT) / 8, 256>>>(out_newxyz, knni);
    // 3. gather + concat
    build_kernel<<<MROWS / 8, 256>>>(feat, knni, out_newxyz, x1);
    // 4. conv1 with fused BN1-stats partials (y1 kept for gemm2 input)
    {
        dim3 grid(MBLK, C1 / 128);
        gemm_kernel<<<grid, 256>>>(x1, W1, b1, y1, C1, nullptr, nullptr, 0,
                                   nullptr, 0, part, 1);
    }
    reduce_kernel<<<32, C1>>>(part, red, C1);
    finalize_kernel<<<1, C1>>>(red, gamma1, beta1, scale, bias, C1);
    // 5. conv2: fused BN1+ReLU input, group-max + BN2-stats epilogue, no Y
    {
        dim3 grid(MBLK, C2 / 128);
        gemm_kernel<<<grid, 256>>>(y1, W2, b2, nullptr, C2, scale, bias, 1,
                                   gmax, 1, part, 1);
    }
    reduce_kernel<<<32, C2>>>(part, red, C2);
    finalize_kernel<<<1, C2>>>(red, gamma2, beta2, scale, bias, C2);
    // 6. BN2+ReLU on pre-reduced max -> output
    maxpool_kernel<<<BATCH * SPT, C2>>>(gmax, scale, bias, out_x);
}

// round 10
// speedup vs baseline: 2.4571x; 1.0460x over previous
#include <cuda_runtime.h>
#include <cuda_bf16.h>
#include <cstdint>
#include <float.h>

// Problem constants (shapes fixed by the dataset)
#define BATCH 4
#define NPT   16384
#define SPT   2048
#define KNN   16
#define DFEAT 125
#define C0    128
#define C1    128
#define C2    256
#define MROWS (BATCH * SPT * KNN)   // 131072 samples through the MLP
#define MBLK  (MROWS / 128)         // 1024 gemm m-blocks (128-row tiles)
#define PSQ_OFF (MBLK * 256)        // sumsq offset inside g_part
#define RSQ_OFF (32 * 256)          // sumsq offset inside g_red

// FPS cluster config: 8 CTAs x 256 threads per batch
#define FC 8
#define FT 256
#define FP (NPT / FC / FT)          // 8 points per thread
#define XT (FC * 8)                 // tx bytes per exchange (8 sources x 8B)
#define FPS_SMEM (3 * NPT * 4)      // full batch xyz in SMEM (192 KB)

// ---------------- scratch (static device globals; no allocation allowed) ----
__device__ float g_y1[(size_t)MROWS * C1];     // conv1 out (raw, pre-BN)
__device__ float g_max[(size_t)BATCH * SPT * C2]; // raw per-group max (8.4MB)
__device__ float g_part[2 * MBLK * 256];       // per-mblock [sum | sumsq]
__device__ float g_red[2 * 32 * 256];          // stage-1 reduced partials
__device__ float g_scale[256];
__device__ float g_bias[256];
__device__ int   g_knn[BATCH * SPT * KNN];
__device__ float g_sx[BATCH * NPT];            // SoA xyz
__device__ float g_sy[BATCH * NPT];
__device__ float g_sz[BATCH * NPT];

// ---------------------------------------------------------------------------
// helpers: DSMEM / mbarrier
// ---------------------------------------------------------------------------
__device__ __forceinline__ uint32_t smem_u32(const void* p) {
    return (uint32_t)__cvta_generic_to_shared(p);
}
__device__ __forceinline__ uint32_t mapa_u32(uint32_t addr, uint32_t rank) {
    uint32_t r;
    asm("mapa.shared::cluster.u32 %0, %1, %2;" : "=r"(r) : "r"(addr), "r"(rank));
    return r;
}
__device__ __forceinline__ void st_async_u64(uint32_t raddr, uint32_t rmbar, uint64_t v) {
    asm volatile("st.async.shared::cluster.mbarrier::complete_tx::bytes.b64 [%0], %1, [%2];"
                 :: "r"(raddr), "l"(v), "r"(rmbar) : "memory");
}
__device__ __forceinline__ void mbar_inval(uint32_t a) {
    asm volatile("mbarrier.inval.shared.b64 [%0];" :: "r"(a) : "memory");
}
__device__ __forceinline__ void mbar_init(uint32_t a, uint32_t cnt) {
    asm volatile("mbarrier.init.shared.b64 [%0], %1;" :: "r"(a), "r"(cnt) : "memory");
}
__device__ __forceinline__ void mbar_arrive_expect(uint32_t a, uint32_t tx) {
    asm volatile("mbarrier.arrive.expect_tx.shared.b64 _, [%0], %1;"
                 :: "r"(a), "r"(tx) : "memory");
}
__device__ __forceinline__ void mbar_wait(uint32_t mbar, uint32_t parity) {
    asm volatile(
        "{\n\t.reg .pred P;\n\t"
        "WAIT_%=:\n\t"
        "mbarrier.try_wait.parity.acquire.cluster.shared::cta.b64 P, [%0], %1, 0x989680;\n\t"
        "@P bra.uni DONE_%=;\n\t"
        "bra.uni WAIT_%=;\n\t"
        "DONE_%=:\n\t}"
        :: "r"(mbar), "r"(parity) : "memory");
}
__device__ __forceinline__ uint64_t u64max(uint64_t a, uint64_t b) {
    return (a > b) ? a : b;
}

// ============================================================================
// 0) AoS -> SoA transpose of xyz (coalesced via smem staging)
// ============================================================================
__global__ __launch_bounds__(256)
void soa_kernel(const float* __restrict__ xyz) {
    __shared__ float buf[768];
    int t = threadIdx.x;
    size_t base = (size_t)blockIdx.x * 768;
#pragma unroll
    for (int r = 0; r < 3; r++) buf[t + 256 * r] = xyz[base + t + 256 * r];
    __syncthreads();
    size_t o = (size_t)blockIdx.x * 256 + t;
    g_sx[o] = buf[t * 3 + 0];
    g_sy[o] = buf[t * 3 + 1];
    g_sz[o] = buf[t * 3 + 2];
}

// ============================================================================
// 1) FPS: 8-CTA x 256-thread cluster per batch. Single u64 candidate key
//    key = (dist_bits << 32) | ~idx  -> u64 max == (max dist, then min idx),
//    exactly jnp's argmax tie-break (dist >= 0 so bits are monotone).
//    mbarrier + st.async exchange (one 8B message per source CTA).
//    Full batch xyz lives in SMEM so winner-coordinate fetch is an LDS.
//    Exact jnp semantics preserved:
//      - no FMA contraction: (dx*dx + dy*dy) + dz*dz with __f*_rn
//      - emits the farthest index of the PREVIOUS step (selected[0] = 0)
//    Exchange e (e>=1) delivers winner e on mbar[e&1], parity (e>>1)&1
//    (dummy completed phase 0 on mbar[0] makes the parity formula uniform).
//    Re-arm for exchange s+2 is issued in warp0 after the s+1 push — safe,
//    since a peer's s+2 store trails my s+1 push by >= one DSMEM RTT+compute.
// ============================================================================
__global__ __launch_bounds__(FT, 1) __cluster_dims__(FC, 1, 1)
void fps_cluster_kernel(float* __restrict__ new_xyz) {
    extern __shared__ float smem[];
    float* shx = smem;
    float* shy = smem + NPT;
    float* shz = smem + 2 * NPT;

    int b = blockIdx.x / FC;
    int rank = blockIdx.x % FC;
    int t = threadIdx.x;
    int w = t >> 5, lane = t & 31;
    int base = rank * (NPT / FC);
    const float* sx = g_sx + (size_t)b * NPT;
    const float* sy = g_sy + (size_t)b * NPT;
    const float* sz = g_sz + (size_t)b * NPT;

    // stage full batch coords into SMEM (winner lookup = LDS broadcast)
    for (int i = t; i < NPT; i += FT) {
        shx[i] = sx[i]; shy[i] = sy[i]; shz[i] = sz[i];
    }

    // own slice in registers
    float px[FP], py[FP], pz[FP], dist[FP];
#pragma unroll
    for (int j = 0; j < FP; j++) {
        int i = base + j * FT + t;
        px[j] = sx[i]; py[j] = sy[i]; pz[j] = sz[i];
        dist[j] = 1e10f;
    }

    __shared__ __align__(8) uint64_t c_slot[2][FC];   // [stage][source rank]
    __shared__ __align__(8) uint64_t mbar[2];
    __shared__ __align__(8) uint64_t s_key[8];        // per-warp winners

    uint32_t mb0 = smem_u32(&mbar[0]);
    uint32_t mb1 = smem_u32(&mbar[1]);

    if (t == 0) {
        mbar_inval(mb0); mbar_inval(mb1);
        mbar_init(mb0, 1); mbar_init(mb1, 1);
        mbar_arrive_expect(mb0, 0);    // dummy: complete phase 0 immediately
        mbar_arrive_expect(mb0, XT);   // arm exchange 2 (phase 1)
        mbar_arrive_expect(mb1, XT);   // arm exchange 1 (phase 0)
    }
    __syncthreads();
    // peers' mbarrier init must be visible before any st.async targets them
    asm volatile("barrier.cluster.arrive.aligned;" ::: "memory");
    asm volatile("barrier.cluster.wait.aligned;" ::: "memory");

    // remote addresses of MY slot in peer CTA 'lane', both stages + mbars
    uint32_t r_s0 = 0, r_s1 = 0, r_m0 = 0, r_m1 = 0;
    if (w == 0 && lane < FC) {
        r_s0 = mapa_u32(smem_u32(&c_slot[0][rank]), lane);
        r_s1 = mapa_u32(smem_u32(&c_slot[1][rank]), lane);
        r_m0 = mapa_u32(mb0, lane);
        r_m1 = mapa_u32(mb1, lane);
    }

    float curx = shx[0], cury = shy[0], curz = shz[0];   // centroid 0 = point 0
    float* out = new_xyz + (size_t)b * SPT * 3;

    for (int s = 0; s < SPT; s++) {
        if (s > 0) {
            // ---- wait exchange s, tree-select winner from 8 u64 keys ----
            uint32_t mb = (s & 1) ? mb1 : mb0;
            mbar_wait(mb, (unsigned)((s >> 1) & 1));
            int bf = s & 1;
            uint64_t k0 = c_slot[bf][0], k1 = c_slot[bf][1];
            uint64_t k2 = c_slot[bf][2], k3 = c_slot[bf][3];
            uint64_t k4 = c_slot[bf][4], k5 = c_slot[bf][5];
            uint64_t k6 = c_slot[bf][6], k7 = c_slot[bf][7];
            uint64_t wk = u64max(u64max(u64max(k0, k1), u64max(k2, k3)),
                                 u64max(u64max(k4, k5), u64max(k6, k7)));
            int wi = (int)(~(uint32_t)wk);
            curx = shx[wi]; cury = shy[wi]; curz = shz[wi];
        }
        if (rank == 0 && t == 0) {
            out[s * 3 + 0] = curx;
            out[s * 3 + 1] = cury;
            out[s * 3 + 2] = curz;
        }
        // ---- update dists + per-thread argmax (strict > keeps smaller idx) --
        float best = -1.0f; int bj = 0;
#pragma unroll
        for (int j = 0; j < FP; j++) {
            float dx = px[j] - curx, dy = py[j] - cury, dz = pz[j] - curz;
            float d = __fadd_rn(__fadd_rn(__fmul_rn(dx, dx), __fmul_rn(dy, dy)),
                                __fmul_rn(dz, dz));
            float nd = fminf(dist[j], d);
            dist[j] = nd;
            bool bt = nd > best;
            best = bt ? nd : best;
            bj = bt ? j : bj;
        }
        unsigned bi = (unsigned)(base + bj * FT + t);
        unsigned vb = __float_as_uint(best);     // dist >= 0 -> monotone bits
        // ---- warp argmax via REDUX: max value bits, then min index ----
        unsigned mv = __reduce_max_sync(0xffffffffu, vb);
        unsigned cnd = (vb == mv) ? ~bi : 0u;    // ~idx: bigger = smaller idx
        unsigned ml = __reduce_max_sync(0xffffffffu, cnd);
        if (lane == 0) s_key[w] = ((uint64_t)mv << 32) | ml;   // uniform value
        __syncthreads();
        // ---- warp0: block argmax over 8 warps + push key + re-arm ----
        if (w == 0) {
            if (s + 1 < SPT) {
                unsigned hi = (lane < 8) ? (unsigned)(s_key[lane] >> 32) : 0u;
                unsigned lo = (lane < 8) ? (unsigned)s_key[lane] : 0u;
                unsigned mv2 = __reduce_max_sync(0xffffffffu, hi);
                unsigned c2 = (hi == mv2) ? lo : 0u;
                unsigned ml2 = __reduce_max_sync(0xffffffffu, c2);
                if (lane < FC) {
                    int st = (s + 1) & 1;
                    uint32_t rs = st ? r_s1 : r_s0;
                    uint32_t rm = st ? r_m1 : r_m0;
                    st_async_u64(rs, rm, ((uint64_t)mv2 << 32) | ml2);
                }
            }
            // re-arm consumed mbar for exchange s+2 (off the consume path)
            if (lane == 8 && s > 0 && s + 2 < SPT)
                mbar_arrive_expect((s & 1) ? mb1 : mb0, XT);
        }
    }
    // keep SMEM alive until every CTA's last consumption is done
    asm volatile("barrier.cluster.arrive.aligned;" ::: "memory");
    asm volatile("barrier.cluster.wait.aligned;" ::: "memory");
}

// ============================================================================
// 2) kNN (k=16). One warp per query; SoA coalesced loads; register top-16
//    per lane over 512 points, then 512 -> 16 selection via shared memory.
//    Only the SET of neighbors matters downstream.
// ============================================================================
__global__ __launch_bounds__(256)
void knn_kernel(const float* __restrict__ new_xyz, int* __restrict__ knn) {
    __shared__ float sd[8][512];
    __shared__ int   si[8][512];
    int w = threadIdx.x >> 5, lane = threadIdx.x & 31;
    int g = blockIdx.x * 8 + w;     // query id 0..8191
    int b = g >> 11;
    const float* sx = g_sx + (size_t)b * NPT;
    const float* sy = g_sy + (size_t)b * NPT;
    const float* sz = g_sz + (size_t)b * NPT;
    float qx = new_xyz[(size_t)g * 3 + 0];
    float qy = new_xyz[(size_t)g * 3 + 1];
    float qz = new_xyz[(size_t)g * 3 + 2];

    float d16[16]; int i16[16];
#pragma unroll
    for (int t = 0; t < 16; t++) { d16[t] = FLT_MAX; i16[t] = 0; }
    float worst = FLT_MAX; int wpos = 0;

    for (int i = 0; i < NPT / 32; i++) {
        int idx = lane + (i << 5);
        float dx = sx[idx] - qx;
        float dy = sy[idx] - qy;
        float dz = sz[idx] - qz;
        float d = dx * dx + dy * dy + dz * dz;
        if (d < worst) {
#pragma unroll
            for (int t = 0; t < 16; t++)
                if (t == wpos) { d16[t] = d; i16[t] = idx; }
            worst = d16[0]; wpos = 0;
#pragma unroll
            for (int t = 1; t < 16; t++)
                if (d16[t] > worst) { worst = d16[t]; wpos = t; }
        }
    }
#pragma unroll
    for (int t = 0; t < 16; t++) {
        sd[w][lane * 16 + t] = d16[t];
        si[w][lane * 16 + t] = i16[t];
    }
    __syncwarp();
    for (int r = 0; r < 16; r++) {
        float mv = FLT_MAX; int mp = 0;
#pragma unroll
        for (int t = 0; t < 16; t++) {
            float v = sd[w][lane * 16 + t];
            if (v < mv) { mv = v; mp = lane * 16 + t; }
        }
#pragma unroll
        for (int off = 16; off; off >>= 1) {
            float ov = __shfl_down_sync(0xffffffffu, mv, off);
            int   op = __shfl_down_sync(0xffffffffu, mp, off);
            if (ov < mv) { mv = ov; mp = op; }
        }
        mp = __shfl_sync(0xffffffffu, mp, 0);
        if (lane == 0) {
            knn[(size_t)g * 16 + r] = si[w][mp];
            sd[w][mp] = FLT_MAX;
        }
        __syncwarp();
    }
}

// ============================================================================
// 3) GEMM: Y[m][c] = sum_k A'[m][k] * W[c][k] + bias, K = 128 fixed.
//    128(M) x 128(N) block tile, 256 threads, 8x8 register tile / thread.
//    Fusions:
//      fuseGather: A row m is built on the fly from knn/feat/xyz (layer 1)
//      fuseA:      A' = relu(A*aScale[k] + aBias[k])  (BN1+ReLU, layer 2)
//      fuseMax:    raw max over each group of 16 rows -> gmax
//      fuseStats:  per-mblock column sum/sumsq partials -> part (BN stats)
//    Y store skipped when Y == nullptr. As/Ws reused for epilogue reductions.
// ============================================================================
__global__ __launch_bounds__(256, 2)
void gemm_kernel(const float* __restrict__ A, const float* __restrict__ W,
                 const float* __restrict__ bias, float* __restrict__ Y, int Nout,
                 const float* __restrict__ aScale, const float* __restrict__ aBias,
                 int fuseA, float* __restrict__ gmax, int fuseMax,
                 float* __restrict__ part, int fuseStats,
                 const float* __restrict__ feat, const int* __restrict__ knni,
                 const float* __restrict__ newxyz, int fuseGather) {
    const int K = 128;
    __shared__ float As[16][128];
    __shared__ float Ws[16][128];
    int m0 = blockIdx.x * 128;
    int c0 = blockIdx.y * 128;
    int tid = threadIdx.x;
    int tx = tid & 15, ty = tid >> 4;
    int lrow = tid & 127, khalf = tid >> 7;

    // gather-mode row sources (layer 1): row n -> neighbor idx of query g
    const float* gfp = nullptr;
    float gx0 = 0.0f, gx1 = 0.0f, gx2 = 0.0f;
    if (fuseGather) {
        int n = m0 + lrow;
        int g = n >> 4;
        int bb = g >> 11;
        int idx = knni[n];
        size_t p = (size_t)bb * NPT + idx;
        gfp = feat + p * DFEAT;
        if (khalf == 0) {
            gx0 = g_sx[p] - newxyz[(size_t)g * 3 + 0];
            gx1 = g_sy[p] - newxyz[(size_t)g * 3 + 1];
            gx2 = g_sz[p] - newxyz[(size_t)g * 3 + 2];
        }
    }

    float acc[8][8];
#pragma unroll
    for (int i = 0; i < 8; i++)
#pragma unroll
        for (int j = 0; j < 8; j++) acc[i][j] = 0.0f;

    for (int k0 = 0; k0 < K; k0 += 16) {
        int kb = khalf * 8;
        if (fuseGather) {
            float av[8];
#pragma unroll
            for (int u = 0; u < 8; u++) {
                int cc = k0 + kb + u - 3;
                av[u] = gfp[cc < 0 ? 0 : cc];
            }
            if (k0 == 0 && khalf == 0) { av[0] = gx0; av[1] = gx1; av[2] = gx2; }
#pragma unroll
            for (int u = 0; u < 8; u++) As[kb + u][lrow] = av[u];
        } else {
            const float* ap = &A[(size_t)(m0 + lrow) * K + k0 + kb];
            float4 a0 = *(const float4*)ap;
            float4 a1 = *(const float4*)(ap + 4);
            if (fuseA) {
                const float* sp = &aScale[k0 + kb];
                const float* bp = &aBias[k0 + kb];
                float4 s0 = *(const float4*)sp, s1 = *(const float4*)(sp + 4);
                float4 q0 = *(const float4*)bp, q1 = *(const float4*)(bp + 4);
                a0.x = fmaxf(fmaf(a0.x, s0.x, q0.x), 0.0f);
                a0.y = fmaxf(fmaf(a0.y, s0.y, q0.y), 0.0f);
                a0.z = fmaxf(fmaf(a0.z, s0.z, q0.z), 0.0f);
                a0.w = fmaxf(fmaf(a0.w, s0.w, q0.w), 0.0f);
                a1.x = fmaxf(fmaf(a1.x, s1.x, q1.x), 0.0f);
                a1.y = fmaxf(fmaf(a1.y, s1.y, q1.y), 0.0f);
                a1.z = fmaxf(fmaf(a1.z, s1.z, q1.z), 0.0f);
                a1.w = fmaxf(fmaf(a1.w, s1.w, q1.w), 0.0f);
            }
            As[kb + 0][lrow] = a0.x; As[kb + 1][lrow] = a0.y;
            As[kb + 2][lrow] = a0.z; As[kb + 3][lrow] = a0.w;
            As[kb + 4][lrow] = a1.x; As[kb + 5][lrow] = a1.y;
            As[kb + 6][lrow] = a1.z; As[kb + 7][lrow] = a1.w;
        }
        {
            const float* wp = &W[(size_t)(c0 + lrow) * K + k0 + kb];
            float4 w0 = *(const float4*)wp;
            float4 w1 = *(const float4*)(wp + 4);
            Ws[kb + 0][lrow] = w0.x; Ws[kb + 1][lrow] = w0.y;
            Ws[kb + 2][lrow] = w0.z; Ws[kb + 3][lrow] = w0.w;
            Ws[kb + 4][lrow] = w1.x; Ws[kb + 5][lrow] = w1.y;
            Ws[kb + 6][lrow] = w1.z; Ws[kb + 7][lrow] = w1.w;
        }
        __syncthreads();
#pragma unroll
        for (int kk = 0; kk < 16; kk++) {
            float4 xa0 = *(const float4*)&As[kk][ty * 8];
            float4 xa1 = *(const float4*)&As[kk][ty * 8 + 4];
            float4 xb0 = *(const float4*)&Ws[kk][tx * 8];
            float4 xb1 = *(const float4*)&Ws[kk][tx * 8 + 4];
            float av[8] = {xa0.x, xa0.y, xa0.z, xa0.w, xa1.x, xa1.y, xa1.z, xa1.w};
            float bv[8] = {xb0.x, xb0.y, xb0.z, xb0.w, xb1.x, xb1.y, xb1.z, xb1.w};
#pragma unroll
            for (int i = 0; i < 8; i++)
#pragma unroll
                for (int j = 0; j < 8; j++) acc[i][j] += av[i] * bv[j];
        }
        __syncthreads();
    }
#pragma unroll
    for (int i = 0; i < 8; i++)
#pragma unroll
        for (int j = 0; j < 8; j++) acc[i][j] += bias[c0 + tx * 8 + j];

    if (Y) {
#pragma unroll
        for (int i = 0; i < 8; i++) {
            size_t row = (size_t)(m0 + ty * 8 + i) * Nout + c0 + tx * 8;
            float4 v0 = {acc[i][0], acc[i][1], acc[i][2], acc[i][3]};
            float4 v1 = {acc[i][4], acc[i][5], acc[i][6], acc[i][7]};
            *(float4*)&Y[row] = v0;
            *(float4*)&Y[row + 4] = v1;
        }
    }
    if (fuseMax) {
        float (*redm)[128] = As;   // reuse (post-sync)
#pragma unroll
        for (int j = 0; j < 8; j++) {
            float m = acc[0][j];
#pragma unroll
            for (int i = 1; i < 8; i++) m = fmaxf(m, acc[i][j]);
            redm[ty][tx * 8 + j] = m;
        }
        __syncthreads();
        if (ty < 8) {   // 8 groups of 16 rows in this 128-row tile
#pragma unroll
            for (int j = 0; j < 8; j++) {
                int c = tx * 8 + j;
                float m = fmaxf(redm[2 * ty][c], redm[2 * ty + 1][c]);
                gmax[(size_t)(m0 / 16 + ty) * Nout + c0 + c] = m;
            }
        }
        __syncthreads();
    }
    if (fuseStats) {
        float (*r0)[128] = As;
        float (*r1)[128] = Ws;
#pragma unroll
        for (int j = 0; j < 8; j++) {
            float s = 0.0f, q = 0.0f;
#pragma unroll
            for (int i = 0; i < 8; i++) { s += acc[i][j]; q += acc[i][j] * acc[i][j]; }
            r0[ty][tx * 8 + j] = s;
            r1[ty][tx * 8 + j] = q;
        }
        __syncthreads();
        if (tid < 128) {          // thread = column within this 128-col tile
            float S = 0.0f, Q = 0.0f;
#pragma unroll
            for (int i = 0; i < 16; i++) { S += r0[i][tid]; Q += r1[i][tid]; }
            size_t o = (size_t)(m0 / 128) * Nout + c0 + tid;
            part[o] = S;
            part[PSQ_OFF + o] = Q;
        }
    }
}

// ============================================================================
// 4) BN stats reduction: stage 1 folds 1024 m-block partials into 32,
//    stage 2 (finalize) folds 32 and emits scale/bias.
// ============================================================================
__global__ void reduce_kernel(const float* __restrict__ part, float* __restrict__ red, int C) {
    int c = threadIdx.x;          // blockDim = C
    int r = blockIdx.x;           // 0..31
    float S = 0.0f, Q = 0.0f;
    for (int m = r * 32; m < r * 32 + 32; m++) {
        size_t o = (size_t)m * C + c;
        S += part[o];
        Q += part[PSQ_OFF + o];
    }
    red[r * C + c] = S;
    red[RSQ_OFF + r * C + c] = Q;
}

__global__ void finalize_kernel(const float* __restrict__ red,
                                const float* __restrict__ gamma,
                                const float* __restrict__ beta,
                                float* __restrict__ scale, float* __restrict__ bias, int C) {
    int c = threadIdx.x;
    float s = 0.0f, q = 0.0f;
    for (int r = 0; r < 32; r++) {
        s += red[r * C + c];
        q += red[RSQ_OFF + r * C + c];
    }
    const float inv = 1.0f / (float)MROWS;
    float m = s * inv;
    float v = q * inv - m * m;
    float sc = gamma[c] * rsqrtf(v + 1e-5f);
    scale[c] = sc;
    bias[c] = beta[c] - m * sc;
}

// ============================================================================
// 5) BN2 + ReLU on the pre-reduced group max (monotone: scale > 0).
// ============================================================================
__global__ __launch_bounds__(256, 4)
void maxpool_kernel(const float* __restrict__ gmax, const float* __restrict__ scale,
                    const float* __restrict__ bias, float* __restrict__ out) {
    int g = blockIdx.x;      // (b,s) 0..8191
    int c = threadIdx.x;     // channel 0..255
    float v = fmaf(gmax[(size_t)g * C2 + c], scale[c], bias[c]);
    out[(size_t)g * C2 + c] = fmaxf(v, 0.0f);
}

// ============================================================================
extern "C" void kernel_launch(void* const* d_in, const int* in_sizes, int n_in,
                              void* d_out, int out_size) {
    const float* xyz    = (const float*)d_in[0];
    const float* feat   = (const float*)d_in[1];
    const float* W1     = (const float*)d_in[2];
    const float* b1     = (const float*)d_in[3];
    const float* gamma1 = (const float*)d_in[4];
    const float* beta1  = (const float*)d_in[5];
    const float* W2     = (const float*)d_in[6];
    const float* b2     = (const float*)d_in[7];
    const float* gamma2 = (const float*)d_in[8];
    const float* beta2  = (const float*)d_in[9];

    float* out = (float*)d_out;
    float* out_newxyz = out;                            // [B,S,3]
    float* out_x      = out + (size_t)BATCH * SPT * 3;  // [B,S,C2]

    float *y1, *gmax, *part, *red, *scale, *bias;
    int *knni;
    cudaGetSymbolAddress((void**)&y1,    g_y1);
    cudaGetSymbolAddress((void**)&gmax,  g_max);
    cudaGetSymbolAddress((void**)&part,  g_part);
    cudaGetSymbolAddress((void**)&red,   g_red);
    cudaGetSymbolAddress((void**)&scale, g_scale);
    cudaGetSymbolAddress((void**)&bias,  g_bias);
    cudaGetSymbolAddress((void**)&knni,  g_knn);

    // 0. SoA transpose of xyz
    soa_kernel<<<(BATCH * NPT) / 256, 256>>>(xyz);
    // 1. FPS (cluster kernel; writes new_xyz directly to output)
    cudaFuncSetAttribute(fps_cluster_kernel,
                         cudaFuncAttributeMaxDynamicSharedMemorySize, FPS_SMEM);
    fps_cluster_kernel<<<BATCH * FC, FT, FPS_SMEM>>>(out_newxyz);
    // 2. kNN
    knn_kernel<<<(BATCH * SPT) / 8, 256>>>(out_newxyz, knni);
    // 3. conv1: fused gather input (no build pass), fused BN1-stats partials
    {
        dim3 grid(MBLK, C1 / 128);
        gemm_kernel<<<grid, 256>>>(nullptr, W1, b1, y1, C1, nullptr, nullptr, 0,
                                   nullptr, 0, part, 1,
                                   feat, knni, out_newxyz, 1);
    }
    reduce_kernel<<<32, C1>>>(part, red, C1);
    finalize_kernel<<<1, C1>>>(red, gamma1, beta1, scale, bias, C1);
    // 4. conv2: fused BN1+ReLU input, group-max + BN2-stats epilogue, no Y
    {
        dim3 grid(MBLK, C2 / 128);
        gemm_kernel<<<grid, 256>>>(y1, W2, b2, nullptr, C2, scale, bias, 1,
                                   gmax, 1, part, 1,
                                   nullptr, nullptr, nullptr, 0);
    }
    reduce_kernel<<<32, C2>>>(part, red, C2);
    finalize_kernel<<<1, C2>>>(red, gamma2, beta2, scale, bias, C2);
    // 5. BN2+ReLU on pre-reduced max -> output
    maxpool_kernel<<<BATCH * SPT, C2>>>(gmax, scale, bias, out_x);
}

// round 11
// speedup vs baseline: 3.3573x; 1.3664x over previous
#include <cuda_runtime.h>
#include <cuda_bf16.h>
#include <cstdint>
#include <float.h>

// Problem constants (shapes fixed by the dataset)
#define BATCH 4
#define NPT   16384
#define SPT   2048
#define KNN   16
#define DFEAT 125
#define C0    128
#define C1    128
#define C2    256
#define MROWS (BATCH * SPT * KNN)   // 131072 samples through the MLP
#define MBLK  (MROWS / 128)         // 1024 gemm m-blocks (128-row tiles)
#define PSQ_OFF (MBLK * 256)        // sumsq offset inside g_part
#define RSQ_OFF (32 * 256)          // sumsq offset inside g_red

// FPS cluster config: 8 CTAs x 256 threads per batch
#define FC 8
#define FT 256
#define FP (NPT / FC / FT)          // 8 points per thread
#define XT (FC * 8)                 // tx bytes per exchange (8 sources x 8B)
#define FPS_SMEM (3 * NPT * 4)      // full batch xyz in SMEM (192 KB)

// ---------------- scratch (static device globals; no allocation allowed) ----
__device__ float g_y1[(size_t)MROWS * C1];     // conv1 out (raw, pre-BN)
__device__ float g_max[(size_t)BATCH * SPT * C2]; // raw per-group max (8.4MB)
__device__ float g_part[2 * MBLK * 256];       // per-mblock [sum | sumsq]
__device__ float g_red[2 * 32 * 256];          // stage-1 reduced partials
__device__ float g_scale[256];
__device__ float g_bias[256];
__device__ int   g_knn[BATCH * SPT * KNN];
__device__ float g_sx[BATCH * NPT];            // SoA xyz
__device__ float g_sy[BATCH * NPT];
__device__ float g_sz[BATCH * NPT];

// ---------------------------------------------------------------------------
// helpers: DSMEM / mbarrier
// ---------------------------------------------------------------------------
__device__ __forceinline__ uint32_t smem_u32(const void* p) {
    return (uint32_t)__cvta_generic_to_shared(p);
}
__device__ __forceinline__ uint32_t mapa_u32(uint32_t addr, uint32_t rank) {
    uint32_t r;
    asm("mapa.shared::cluster.u32 %0, %1, %2;" : "=r"(r) : "r"(addr), "r"(rank));
    return r;
}
__device__ __forceinline__ void st_async_u64(uint32_t raddr, uint32_t rmbar, uint64_t v) {
    asm volatile("st.async.shared::cluster.mbarrier::complete_tx::bytes.b64 [%0], %1, [%2];"
                 :: "r"(raddr), "l"(v), "r"(rmbar) : "memory");
}
__device__ __forceinline__ void mbar_inval(uint32_t a) {
    asm volatile("mbarrier.inval.shared.b64 [%0];" :: "r"(a) : "memory");
}
__device__ __forceinline__ void mbar_init(uint32_t a, uint32_t cnt) {
    asm volatile("mbarrier.init.shared.b64 [%0], %1;" :: "r"(a), "r"(cnt) : "memory");
}
__device__ __forceinline__ void mbar_arrive_expect(uint32_t a, uint32_t tx) {
    asm volatile("mbarrier.arrive.expect_tx.shared.b64 _, [%0], %1;"
                 :: "r"(a), "r"(tx) : "memory");
}
__device__ __forceinline__ void mbar_wait(uint32_t mbar, uint32_t parity) {
    asm volatile(
        "{\n\t.reg .pred P;\n\t"
        "WAIT_%=:\n\t"
        "mbarrier.try_wait.parity.acquire.cluster.shared::cta.b64 P, [%0], %1, 0x989680;\n\t"
        "@P bra.uni DONE_%=;\n\t"
        "bra.uni WAIT_%=;\n\t"
        "DONE_%=:\n\t}"
        :: "r"(mbar), "r"(parity) : "memory");
}
__device__ __forceinline__ uint64_t u64max(uint64_t a, uint64_t b) {
    return (a > b) ? a : b;
}

// ============================================================================
// 0) AoS -> SoA transpose of xyz (coalesced via smem staging)
// ============================================================================
__global__ __launch_bounds__(256)
void soa_kernel(const float* __restrict__ xyz) {
    __shared__ float buf[768];
    int t = threadIdx.x;
    size_t base = (size_t)blockIdx.x * 768;
#pragma unroll
    for (int r = 0; r < 3; r++) buf[t + 256 * r] = xyz[base + t + 256 * r];
    __syncthreads();
    size_t o = (size_t)blockIdx.x * 256 + t;
    g_sx[o] = buf[t * 3 + 0];
    g_sy[o] = buf[t * 3 + 1];
    g_sz[o] = buf[t * 3 + 2];
}

// ============================================================================
// 1) FPS (unchanged from R10 — best measured variant).
// ============================================================================
__global__ __launch_bounds__(FT, 1) __cluster_dims__(FC, 1, 1)
void fps_cluster_kernel(float* __restrict__ new_xyz) {
    extern __shared__ float smem[];
    float* shx = smem;
    float* shy = smem + NPT;
    float* shz = smem + 2 * NPT;

    int b = blockIdx.x / FC;
    int rank = blockIdx.x % FC;
    int t = threadIdx.x;
    int w = t >> 5, lane = t & 31;
    int base = rank * (NPT / FC);
    const float* sx = g_sx + (size_t)b * NPT;
    const float* sy = g_sy + (size_t)b * NPT;
    const float* sz = g_sz + (size_t)b * NPT;

    for (int i = t; i < NPT; i += FT) {
        shx[i] = sx[i]; shy[i] = sy[i]; shz[i] = sz[i];
    }

    float px[FP], py[FP], pz[FP], dist[FP];
#pragma unroll
    for (int j = 0; j < FP; j++) {
        int i = base + j * FT + t;
        px[j] = sx[i]; py[j] = sy[i]; pz[j] = sz[i];
        dist[j] = 1e10f;
    }

    __shared__ __align__(8) uint64_t c_slot[2][FC];
    __shared__ __align__(8) uint64_t mbar[2];
    __shared__ __align__(8) uint64_t s_key[8];

    uint32_t mb0 = smem_u32(&mbar[0]);
    uint32_t mb1 = smem_u32(&mbar[1]);

    if (t == 0) {
        mbar_inval(mb0); mbar_inval(mb1);
        mbar_init(mb0, 1); mbar_init(mb1, 1);
        mbar_arrive_expect(mb0, 0);
        mbar_arrive_expect(mb0, XT);
        mbar_arrive_expect(mb1, XT);
    }
    __syncthreads();
    asm volatile("barrier.cluster.arrive.aligned;" ::: "memory");
    asm volatile("barrier.cluster.wait.aligned;" ::: "memory");

    uint32_t r_s0 = 0, r_s1 = 0, r_m0 = 0, r_m1 = 0;
    if (w == 0 && lane < FC) {
        r_s0 = mapa_u32(smem_u32(&c_slot[0][rank]), lane);
        r_s1 = mapa_u32(smem_u32(&c_slot[1][rank]), lane);
        r_m0 = mapa_u32(mb0, lane);
        r_m1 = mapa_u32(mb1, lane);
    }

    float curx = shx[0], cury = shy[0], curz = shz[0];
    float* out = new_xyz + (size_t)b * SPT * 3;

    for (int s = 0; s < SPT; s++) {
        if (s > 0) {
            uint32_t mb = (s & 1) ? mb1 : mb0;
            mbar_wait(mb, (unsigned)((s >> 1) & 1));
            int bf = s & 1;
            uint64_t k0 = c_slot[bf][0], k1 = c_slot[bf][1];
            uint64_t k2 = c_slot[bf][2], k3 = c_slot[bf][3];
            uint64_t k4 = c_slot[bf][4], k5 = c_slot[bf][5];
            uint64_t k6 = c_slot[bf][6], k7 = c_slot[bf][7];
            uint64_t wk = u64max(u64max(u64max(k0, k1), u64max(k2, k3)),
                                 u64max(u64max(k4, k5), u64max(k6, k7)));
            int wi = (int)(~(uint32_t)wk);
            curx = shx[wi]; cury = shy[wi]; curz = shz[wi];
        }
        if (rank == 0 && t == 0) {
            out[s * 3 + 0] = curx;
            out[s * 3 + 1] = cury;
            out[s * 3 + 2] = curz;
        }
        float best = -1.0f; int bj = 0;
#pragma unroll
        for (int j = 0; j < FP; j++) {
            float dx = px[j] - curx, dy = py[j] - cury, dz = pz[j] - curz;
            float d = __fadd_rn(__fadd_rn(__fmul_rn(dx, dx), __fmul_rn(dy, dy)),
                                __fmul_rn(dz, dz));
            float nd = fminf(dist[j], d);
            dist[j] = nd;
            bool bt = nd > best;
            best = bt ? nd : best;
            bj = bt ? j : bj;
        }
        unsigned bi = (unsigned)(base + bj * FT + t);
        unsigned vb = __float_as_uint(best);
        unsigned mv = __reduce_max_sync(0xffffffffu, vb);
        unsigned cnd = (vb == mv) ? ~bi : 0u;
        unsigned ml = __reduce_max_sync(0xffffffffu, cnd);
        if (lane == 0) s_key[w] = ((uint64_t)mv << 32) | ml;
        __syncthreads();
        if (w == 0) {
            if (s + 1 < SPT) {
                unsigned hi = (lane < 8) ? (unsigned)(s_key[lane] >> 32) : 0u;
                unsigned lo = (lane < 8) ? (unsigned)s_key[lane] : 0u;
                unsigned mv2 = __reduce_max_sync(0xffffffffu, hi);
                unsigned c2 = (hi == mv2) ? lo : 0u;
                unsigned ml2 = __reduce_max_sync(0xffffffffu, c2);
                if (lane < FC) {
                    int st = (s + 1) & 1;
                    uint32_t rs = st ? r_s1 : r_s0;
                    uint32_t rm = st ? r_m1 : r_m0;
                    st_async_u64(rs, rm, ((uint64_t)mv2 << 32) | ml2);
                }
            }
            if (lane == 8 && s > 0 && s + 2 < SPT)
                mbar_arrive_expect((s & 1) ? mb1 : mb0, XT);
        }
    }
    asm volatile("barrier.cluster.arrive.aligned;" ::: "memory");
    asm volatile("barrier.cluster.wait.aligned;" ::: "memory");
}

// ============================================================================
// 2) kNN (k=16): warp-collective top-16. Lanes 0..15 each own one entry
//    (value tv, index tix); lanes 16..31 hold tv=0 so they never win the
//    bit-max (all dists >= 0 -> monotone u32 bits). Per 32-point round one
//    ballot vs the warp-global 16th-best; insertions are rare events handled
//    warp-uniformly via shfl + REDUX. No smem, no divergent per-lane insert.
// ============================================================================
__global__ __launch_bounds__(256)
void knn_kernel(const float* __restrict__ new_xyz, int* __restrict__ knn) {
    int w = threadIdx.x >> 5, lane = threadIdx.x & 31;
    int g = blockIdx.x * 8 + w;     // query id 0..8191
    int b = g >> 11;
    const float* sx = g_sx + (size_t)b * NPT;
    const float* sy = g_sy + (size_t)b * NPT;
    const float* sz = g_sz + (size_t)b * NPT;
    float qx = new_xyz[(size_t)g * 3 + 0];
    float qy = new_xyz[(size_t)g * 3 + 1];
    float qz = new_xyz[(size_t)g * 3 + 2];

    float tv = (lane < 16) ? FLT_MAX : 0.0f;   // owned top entry (lanes 0..15)
    int   tix = 0;
    float ww = FLT_MAX;                        // warp-global 16th best

    for (int i = 0; i < NPT / 32; i++) {
        int base = i << 5;
        float dx = sx[base + lane] - qx;
        float dy = sy[base + lane] - qy;
        float dz = sz[base + lane] - qz;
        float d = dx * dx + dy * dy + dz * dz;
        unsigned m = __ballot_sync(0xffffffffu, d < ww);
        while (m) {                            // rare after warm-up
            int src = __ffs(m) - 1; m &= m - 1;
            float dc = __shfl_sync(0xffffffffu, d, src);
            if (dc < ww) {
                unsigned mv = __reduce_max_sync(0xffffffffu, __float_as_uint(tv));
                unsigned own = __ballot_sync(0xffffffffu, __float_as_uint(tv) == mv) & 0xffffu;
                if (lane == __ffs(own) - 1) { tv = dc; tix = base + src; }
                ww = __uint_as_float(__reduce_max_sync(0xffffffffu, __float_as_uint(tv)));
            }
        }
    }
    if (lane < 16) knn[(size_t)g * 16 + lane] = tix;
}

// ============================================================================
// 3) GEMM: Y[m][c] = sum_k A'[m][k] * W[c][k] + bias, K = 128 fixed.
//    128x128 tile, 256 threads, 8x8 register tile. A-side software pipeline:
//    next k-tile of A prefetched into registers during compute (A streams
//    67MB; W is L1-resident so its exposure is ~L1-hit latency only).
//    Fusions: fuseGather (layer-1 on-the-fly gather), fuseA (BN1+ReLU on A),
//    fuseMax (group-of-16 max -> gmax), fuseStats (BN partials -> part).
// ============================================================================
__global__ __launch_bounds__(256, 2)
void gemm_kernel(const float* __restrict__ A, const float* __restrict__ W,
                 const float* __restrict__ bias, float* __restrict__ Y, int Nout,
                 const float* __restrict__ aScale, const float* __restrict__ aBias,
                 int fuseA, float* __restrict__ gmax, int fuseMax,
                 float* __restrict__ part, int fuseStats,
                 const float* __restrict__ feat, const int* __restrict__ knni,
                 const float* __restrict__ newxyz, int fuseGather) {
    const int K = 128;
    __shared__ float As[16][128];
    __shared__ float Ws[16][128];
    int m0 = blockIdx.x * 128;
    int c0 = blockIdx.y * 128;
    int tid = threadIdx.x;
    int tx = tid & 15, ty = tid >> 4;
    int lrow = tid & 127, khalf = tid >> 7;
    int kb = khalf * 8;

    // gather-mode row sources (layer 1)
    const float* gfp = nullptr;
    float gx0 = 0.0f, gx1 = 0.0f, gx2 = 0.0f;
    if (fuseGather) {
        int n = m0 + lrow;
        int g = n >> 4;
        int bb = g >> 11;
        int idx = knni[n];
        size_t p = (size_t)bb * NPT + idx;
        gfp = feat + p * DFEAT;
        if (khalf == 0) {
            gx0 = g_sx[p] - newxyz[(size_t)g * 3 + 0];
            gx1 = g_sy[p] - newxyz[(size_t)g * 3 + 1];
            gx2 = g_sz[p] - newxyz[(size_t)g * 3 + 2];
        }
    }

    float acc[8][8];
#pragma unroll
    for (int i = 0; i < 8; i++)
#pragma unroll
        for (int j = 0; j < 8; j++) acc[i][j] = 0.0f;

    // ---- prefetch A k-tile 0 into registers ----
    float ar[8];
    if (fuseGather) {
#pragma unroll
        for (int u = 0; u < 8; u++) {
            int cc = kb + u - 3;
            ar[u] = gfp[cc < 0 ? 0 : cc];
        }
        if (khalf == 0) { ar[0] = gx0; ar[1] = gx1; ar[2] = gx2; }
    } else {
        const float* ap = &A[(size_t)(m0 + lrow) * K + kb];
        float4 a0 = *(const float4*)ap;
        float4 a1 = *(const float4*)(ap + 4);
        ar[0] = a0.x; ar[1] = a0.y; ar[2] = a0.z; ar[3] = a0.w;
        ar[4] = a1.x; ar[5] = a1.y; ar[6] = a1.z; ar[7] = a1.w;
    }

    for (int kt = 0; kt < 8; kt++) {
        int k0 = kt * 16;
        // store A (with optional fused BN1+ReLU), load+store W (L1-resident)
#pragma unroll
        for (int u = 0; u < 8; u++) {
            float x = ar[u];
            if (fuseA)
                x = fmaxf(fmaf(x, aScale[k0 + kb + u], aBias[k0 + kb + u]), 0.0f);
            As[kb + u][lrow] = x;
        }
        {
            const float* wp = &W[(size_t)(c0 + lrow) * K + k0 + kb];
            float4 w0 = *(const float4*)wp;
            float4 w1 = *(const float4*)(wp + 4);
            Ws[kb + 0][lrow] = w0.x; Ws[kb + 1][lrow] = w0.y;
            Ws[kb + 2][lrow] = w0.z; Ws[kb + 3][lrow] = w0.w;
            Ws[kb + 4][lrow] = w1.x; Ws[kb + 5][lrow] = w1.y;
            Ws[kb + 6][lrow] = w1.z; Ws[kb + 7][lrow] = w1.w;
        }
        __syncthreads();
        // issue next A-tile loads so they fly during compute
        if (kt < 7) {
            int kn = k0 + 16;
            if (fuseGather) {
#pragma unroll
                for (int u = 0; u < 8; u++) ar[u] = gfp[kn + kb + u - 3];
            } else {
                const float* ap = &A[(size_t)(m0 + lrow) * K + kn + kb];
                float4 a0 = *(const float4*)ap;
                float4 a1 = *(const float4*)(ap + 4);
                ar[0] = a0.x; ar[1] = a0.y; ar[2] = a0.z; ar[3] = a0.w;
                ar[4] = a1.x; ar[5] = a1.y; ar[6] = a1.z; ar[7] = a1.w;
            }
        }
#pragma unroll
        for (int kk = 0; kk < 16; kk++) {
            float4 xa0 = *(const float4*)&As[kk][ty * 8];
            float4 xa1 = *(const float4*)&As[kk][ty * 8 + 4];
            float4 xb0 = *(const float4*)&Ws[kk][tx * 8];
            float4 xb1 = *(const float4*)&Ws[kk][tx * 8 + 4];
            float av[8] = {xa0.x, xa0.y, xa0.z, xa0.w, xa1.x, xa1.y, xa1.z, xa1.w};
            float bv[8] = {xb0.x, xb0.y, xb0.z, xb0.w, xb1.x, xb1.y, xb1.z, xb1.w};
#pragma unroll
            for (int i = 0; i < 8; i++)
#pragma unroll
                for (int j = 0; j < 8; j++) acc[i][j] += av[i] * bv[j];
        }
        __syncthreads();
    }
#pragma unroll
    for (int i = 0; i < 8; i++)
#pragma unroll
        for (int j = 0; j < 8; j++) acc[i][j] += bias[c0 + tx * 8 + j];

    if (Y) {
#pragma unroll
        for (int i = 0; i < 8; i++) {
            size_t row = (size_t)(m0 + ty * 8 + i) * Nout + c0 + tx * 8;
            float4 v0 = {acc[i][0], acc[i][1], acc[i][2], acc[i][3]};
            float4 v1 = {acc[i][4], acc[i][5], acc[i][6], acc[i][7]};
            *(float4*)&Y[row] = v0;
            *(float4*)&Y[row + 4] = v1;
        }
    }
    if (fuseMax) {
        float (*redm)[128] = As;
#pragma unroll
        for (int j = 0; j < 8; j++) {
            float m = acc[0][j];
#pragma unroll
            for (int i = 1; i < 8; i++) m = fmaxf(m, acc[i][j]);
            redm[ty][tx * 8 + j] = m;
        }
        __syncthreads();
        if (ty < 8) {
#pragma unroll
            for (int j = 0; j < 8; j++) {
                int c = tx * 8 + j;
                float m = fmaxf(redm[2 * ty][c], redm[2 * ty + 1][c]);
                gmax[(size_t)(m0 / 16 + ty) * Nout + c0 + c] = m;
            }
        }
        __syncthreads();
    }
    if (fuseStats) {
        float (*r0)[128] = As;
        float (*r1)[128] = Ws;
#pragma unroll
        for (int j = 0; j < 8; j++) {
            float s = 0.0f, q = 0.0f;
#pragma unroll
            for (int i = 0; i < 8; i++) { s += acc[i][j]; q += acc[i][j] * acc[i][j]; }
            r0[ty][tx * 8 + j] = s;
            r1[ty][tx * 8 + j] = q;
        }
        __syncthreads();
        if (tid < 128) {
            float S = 0.0f, Q = 0.0f;
#pragma unroll
            for (int i = 0; i < 16; i++) { S += r0[i][tid]; Q += r1[i][tid]; }
            size_t o = (size_t)(m0 / 128) * Nout + c0 + tid;
            part[o] = S;
            part[PSQ_OFF + o] = Q;
        }
    }
}

// ============================================================================
// 4) BN stats reduction: stage 1 folds 1024 m-block partials into 32,
//    stage 2 (finalize) folds 32 and emits scale/bias.
// ============================================================================
__global__ void reduce_kernel(const float* __restrict__ part, float* __restrict__ red, int C) {
    int c = threadIdx.x;
    int r = blockIdx.x;
    float S = 0.0f, Q = 0.0f;
    for (int m = r * 32; m < r * 32 + 32; m++) {
        size_t o = (size_t)m * C + c;
        S += part[o];
        Q += part[PSQ_OFF + o];
    }
    red[r * C + c] = S;
    red[RSQ_OFF + r * C + c] = Q;
}

__global__ void finalize_kernel(const float* __restrict__ red,
                                const float* __restrict__ gamma,
                                const float* __restrict__ beta,
                                float* __restrict__ scale, float* __restrict__ bias, int C) {
    int c = threadIdx.x;
    float s = 0.0f, q = 0.0f;
    for (int r = 0; r < 32; r++) {
        s += red[r * C + c];
        q += red[RSQ_OFF + r * C + c];
    }
    const float inv = 1.0f / (float)MROWS;
    float m = s * inv;
    float v = q * inv - m * m;
    float sc = gamma[c] * rsqrtf(v + 1e-5f);
    scale[c] = sc;
    bias[c] = beta[c] - m * sc;
}

// ============================================================================
// 5) BN2 + ReLU on the pre-reduced group max (monotone: scale > 0).
// ============================================================================
__global__ __launch_bounds__(256, 4)
void maxpool_kernel(const float* __restrict__ gmax, const float* __restrict__ scale,
                    const float* __restrict__ bias, float* __restrict__ out) {
    int g = blockIdx.x;
    int c = threadIdx.x;
    float v = fmaf(gmax[(size_t)g * C2 + c], scale[c], bias[c]);
    out[(size_t)g * C2 + c] = fmaxf(v, 0.0f);
}

// ============================================================================
extern "C" void kernel_launch(void* const* d_in, const int* in_sizes, int n_in,
                              void* d_out, int out_size) {
    const float* xyz    = (const float*)d_in[0];
    const float* feat   = (const float*)d_in[1];
    const float* W1     = (const float*)d_in[2];
    const float* b1     = (const float*)d_in[3];
    const float* gamma1 = (const float*)d_in[4];
    const float* beta1  = (const float*)d_in[5];
    const float* W2     = (const float*)d_in[6];
    const float* b2     = (const float*)d_in[7];
    const float* gamma2 = (const float*)d_in[8];
    const float* beta2  = (const float*)d_in[9];

    float* out = (float*)d_out;
    float* out_newxyz = out;                            // [B,S,3]
    float* out_x      = out + (size_t)BATCH * SPT * 3;  // [B,S,C2]

    float *y1, *gmax, *part, *red, *scale, *bias;
    int *knni;
    cudaGetSymbolAddress((void**)&y1,    g_y1);
    cudaGetSymbolAddress((void**)&gmax,  g_max);
    cudaGetSymbolAddress((void**)&part,  g_part);
    cudaGetSymbolAddress((void**)&red,   g_red);
    cudaGetSymbolAddress((void**)&scale, g_scale);
    cudaGetSymbolAddress((void**)&bias,  g_bias);
    cudaGetSymbolAddress((void**)&knni,  g_knn);

    // 0. SoA transpose of xyz
    soa_kernel<<<(BATCH * NPT) / 256, 256>>>(xyz);
    // 1. FPS (cluster kernel; writes new_xyz directly to output)
    cudaFuncSetAttribute(fps_cluster_kernel,
                         cudaFuncAttributeMaxDynamicSharedMemorySize, FPS_SMEM);
    fps_cluster_kernel<<<BATCH * FC, FT, FPS_SMEM>>>(out_newxyz);
    // 2. kNN (warp-collective top-16)
    knn_kernel<<<(BATCH * SPT) / 8, 256>>>(out_newxyz, knni);
    // 3. conv1: fused gather input, fused BN1-stats partials
    {
        dim3 grid(MBLK, C1 / 128);
        gemm_kernel<<<grid, 256>>>(nullptr, W1, b1, y1, C1, nullptr, nullptr, 0,
                                   nullptr, 0, part, 1,
                                   feat, knni, out_newxyz, 1);
    }
    reduce_kernel<<<32, C1>>>(part, red, C1);
    finalize_kernel<<<1, C1>>>(red, gamma1, beta1, scale, bias, C1);
    // 4. conv2: fused BN1+ReLU input, group-max + BN2-stats epilogue, no Y
    {
        dim3 grid(MBLK, C2 / 128);
        gemm_kernel<<<grid, 256>>>(y1, W2, b2, nullptr, C2, scale, bias, 1,
                                   gmax, 1, part, 1,
                                   nullptr, nullptr, nullptr, 0);
    }
    reduce_kernel<<<32, C2>>>(part, red, C2);
    finalize_kernel<<<1, C2>>>(red, gamma2, beta2, scale, bias, C2);
    // 5. BN2+ReLU on pre-reduced max -> output
    maxpool_kernel<<<BATCH * SPT, C2>>>(gmax, scale, bias, out_x);
}